// round 3
// baseline (speedup 1.0000x reference)
#include <cuda_runtime.h>
#include <math.h>

#define DIMC   1024
#define NH     16
#define NKV    4
#define GROUPS 4
#define HD     64
#define SEQ    2048
#define BATCH  2
#define ROWS   (BATCH*SEQ)      /* 4096 */
#define KVC    (2*NKV*HD)       /* 512  */
#define QKVN   (DIMC + KVC)     /* 1536 */
#define SCALE  0.125f           /* 64^-0.5 */

// Scratch (allocation-free rule: __device__ globals, referenced directly in kernels)
__device__ float g_q [ROWS*DIMC];   // Q  [4096,1024]
__device__ float g_kv[ROWS*KVC];    // KV [4096,512] : k at +kvh*64, v at +256+kvh*64
__device__ float g_ao[ROWS*DIMC];   // attention output [4096,1024]

// ---------------------------------------------------------------------------
// Shared GEMM body: C[m0.., col0..] (+bias) = A[M,K] @ Bw[rows nb.., K]^T
// 64x64 block tile, K-tile 32, 256 threads, 4x4 microtile per thread.
// ---------------------------------------------------------------------------
__device__ __forceinline__ void gemm_body(
    const float* __restrict__ A, const float* __restrict__ Bw,
    const float* __restrict__ bias, float* __restrict__ C,
    int ldc, int K, int m0, int nb)
{
    __shared__ float As[32*68];   // As[k*68 + m]
    __shared__ float Bs[32*68];   // Bs[k*68 + n]

    const int tid = threadIdx.x;
    const int tm = (tid >> 4) << 2;   // 0..60
    const int tn = (tid & 15) << 2;   // 0..60

    float acc[4][4] = {};

    for (int k0 = 0; k0 < K; k0 += 32) {
        #pragma unroll
        for (int i = 0; i < 2; i++) {
            int f = tid + i * 256;          // 512 float4 per operand tile
            int r = f >> 3;                 // 0..63
            int c = (f & 7) << 2;           // 0..28
            float4 a = *(const float4*)(A + (size_t)(m0 + r) * K + k0 + c);
            As[(c+0)*68 + r] = a.x; As[(c+1)*68 + r] = a.y;
            As[(c+2)*68 + r] = a.z; As[(c+3)*68 + r] = a.w;
            float4 b = *(const float4*)(Bw + (size_t)(nb + r) * K + k0 + c);
            Bs[(c+0)*68 + r] = b.x; Bs[(c+1)*68 + r] = b.y;
            Bs[(c+2)*68 + r] = b.z; Bs[(c+3)*68 + r] = b.w;
        }
        __syncthreads();

        #pragma unroll 8
        for (int kk = 0; kk < 32; kk++) {
            float4 af = *(const float4*)&As[kk*68 + tm];
            float4 bf = *(const float4*)&Bs[kk*68 + tn];
            acc[0][0] += af.x*bf.x; acc[0][1] += af.x*bf.y; acc[0][2] += af.x*bf.z; acc[0][3] += af.x*bf.w;
            acc[1][0] += af.y*bf.x; acc[1][1] += af.y*bf.y; acc[1][2] += af.y*bf.z; acc[1][3] += af.y*bf.w;
            acc[2][0] += af.z*bf.x; acc[2][1] += af.z*bf.y; acc[2][2] += af.z*bf.z; acc[2][3] += af.z*bf.w;
            acc[3][0] += af.w*bf.x; acc[3][1] += af.w*bf.y; acc[3][2] += af.w*bf.z; acc[3][3] += af.w*bf.w;
        }
        __syncthreads();
    }

    float4 bb = make_float4(0.f, 0.f, 0.f, 0.f);
    if (bias) bb = *(const float4*)(bias + nb + tn);
    #pragma unroll
    for (int i = 0; i < 4; i++) {
        float4 o;
        o.x = acc[i][0] + bb.x; o.y = acc[i][1] + bb.y;
        o.z = acc[i][2] + bb.z; o.w = acc[i][3] + bb.w;
        *(float4*)(C + (size_t)(m0 + tm + i) * ldc + nb + tn) = o;
    }
}

// Fused QKV projection: block column < 1024 -> Q = x Wq^T, else KV = x Wkv^T
__global__ void __launch_bounds__(256) qkv_gemm(
    const float* __restrict__ x, const float* __restrict__ Wq,
    const float* __restrict__ Wkv)
{
    const int m0 = blockIdx.y * 64;
    const int n0 = blockIdx.x * 64;
    if (n0 < DIMC) gemm_body(x, Wq,  nullptr, g_q,  DIMC, DIMC, m0, n0);
    else           gemm_body(x, Wkv, nullptr, g_kv, KVC,  DIMC, m0, n0 - DIMC);
}

// Output projection: out = g_ao @ Wproj^T + bproj
__global__ void __launch_bounds__(256) proj_gemm(
    const float* __restrict__ Wproj, const float* __restrict__ bproj,
    float* __restrict__ out)
{
    gemm_body(g_ao, Wproj, bproj, out, DIMC, DIMC, blockIdx.y * 64, blockIdx.x * 64);
}

// ---------------------------------------------------------------------------
// Flash attention, fp32, static smem (<=48KB). One CTA = 64 Q rows, j-tile 32.
// ---------------------------------------------------------------------------
#define LDQ 68   /* stride for r / d-major tiles */
#define LDS 36   /* stride for 32-wide j tiles   */

__global__ void __launch_bounds__(256) attn_kernel()
{
    __shared__ float Qs[64*LDQ];   // Qs[d*LDQ + r]  (pre-scaled)    17408 B
    __shared__ float Ks[64*LDS];   // Ks[d*LDS + j]                   9216 B
    __shared__ float Vs[32*LDQ];   // Vs[j*LDQ + d]                   8704 B
    __shared__ float Ss[64*LDS];   // Ss[r*LDS + j]                   9216 B
    __shared__ float m_s[64], l_s[64], a_s[64];

    const int tid = threadIdx.x;
    const int q0  = blockIdx.x * 64;
    const int h   = blockIdx.y;
    const int b   = blockIdx.z;
    const int kvh = h >> 2;          // h / GROUPS

    const int tm  = (tid >> 4) << 2; // S rows / O rows: 0..60
    const int tnS = (tid & 15) << 1; // S cols: 0..30
    const int tnD = (tid & 15) << 2; // O d cols: 0..60
    const int r   = tid >> 2;        // softmax row
    const int jq  = tid & 3;         // softmax eighth (8 cols)

    // Load + transpose + pre-scale Q tile (64 rows x 64 d)
    #pragma unroll
    for (int i = 0; i < 4; i++) {
        int f  = tid + i * 256;      // 1024 float4
        int rr = f >> 4;
        int c  = (f & 15) << 2;
        float4 q = *(const float4*)(g_q + (size_t)(b*SEQ + q0 + rr) * DIMC + h*HD + c);
        Qs[(c+0)*LDQ + rr] = q.x * SCALE; Qs[(c+1)*LDQ + rr] = q.y * SCALE;
        Qs[(c+2)*LDQ + rr] = q.z * SCALE; Qs[(c+3)*LDQ + rr] = q.w * SCALE;
    }
    if (tid < 64) { m_s[tid] = -INFINITY; l_s[tid] = 0.f; }

    float oacc[4][4] = {};
    __syncthreads();

    for (int j0 = 0; j0 < SEQ; j0 += 32) {
        // Load K (transposed, 32 rows) and V (row-major, 32 rows)
        #pragma unroll
        for (int i = 0; i < 2; i++) {
            int f  = tid + i * 256;  // 512 float4 each
            int rr = f >> 4;         // 0..31
            int c  = (f & 15) << 2;  // 0..60
            const float* kvb = g_kv + (size_t)(b*SEQ + j0 + rr) * KVC + kvh*HD;
            float4 kk = *(const float4*)(kvb + c);
            Ks[(c+0)*LDS + rr] = kk.x; Ks[(c+1)*LDS + rr] = kk.y;
            Ks[(c+2)*LDS + rr] = kk.z; Ks[(c+3)*LDS + rr] = kk.w;
            float4 vv = *(const float4*)(kvb + 256 + c);
            *(float4*)&Vs[rr*LDQ + c] = vv;
        }
        __syncthreads();

        // S = Q K^T : 4x2 microtile over d
        float sacc[4][2] = {};
        #pragma unroll 8
        for (int d = 0; d < 64; d++) {
            float4 qf = *(const float4*)&Qs[d*LDQ + tm];
            float b0 = Ks[d*LDS + tnS];
            float b1 = Ks[d*LDS + tnS + 1];
            sacc[0][0] += qf.x*b0; sacc[0][1] += qf.x*b1;
            sacc[1][0] += qf.y*b0; sacc[1][1] += qf.y*b1;
            sacc[2][0] += qf.z*b0; sacc[2][1] += qf.z*b1;
            sacc[3][0] += qf.w*b0; sacc[3][1] += qf.w*b1;
        }
        #pragma unroll
        for (int i = 0; i < 4; i++)
            *(float2*)&Ss[(tm+i)*LDS + tnS] = make_float2(sacc[i][0], sacc[i][1]);
        __syncthreads();

        // Online softmax over 32 cols: 4 threads per row, 8 cols each
        {
            float* prow = &Ss[r*LDS + jq*8];
            float mx = -INFINITY;
            #pragma unroll
            for (int j = 0; j < 8; j++) mx = fmaxf(mx, prow[j]);
            mx = fmaxf(mx, __shfl_xor_sync(0xffffffffu, mx, 1));
            mx = fmaxf(mx, __shfl_xor_sync(0xffffffffu, mx, 2));
            float mold = m_s[r];
            float mnew = fmaxf(mold, mx);
            float lsum = 0.f;
            #pragma unroll
            for (int j = 0; j < 8; j++) {
                float p = __expf(prow[j] - mnew);
                prow[j] = p;
                lsum += p;
            }
            lsum += __shfl_xor_sync(0xffffffffu, lsum, 1);
            lsum += __shfl_xor_sync(0xffffffffu, lsum, 2);
            if (jq == 0) {
                float alpha = __expf(mold - mnew);
                l_s[r] = l_s[r] * alpha + lsum;
                m_s[r] = mnew;
                a_s[r] = alpha;
            }
        }
        __syncthreads();

        // O = O*alpha + P V : 4x4 microtile over j (32)
        {
            float al[4];
            #pragma unroll
            for (int i = 0; i < 4; i++) al[i] = a_s[tm+i];
            #pragma unroll
            for (int i = 0; i < 4; i++)
                #pragma unroll
                for (int j = 0; j < 4; j++) oacc[i][j] *= al[i];

            #pragma unroll 8
            for (int j = 0; j < 32; j++) {
                float4 vv = *(const float4*)&Vs[j*LDQ + tnD];
                float p0 = Ss[(tm+0)*LDS + j];
                float p1 = Ss[(tm+1)*LDS + j];
                float p2 = Ss[(tm+2)*LDS + j];
                float p3 = Ss[(tm+3)*LDS + j];
                oacc[0][0] += p0*vv.x; oacc[0][1] += p0*vv.y; oacc[0][2] += p0*vv.z; oacc[0][3] += p0*vv.w;
                oacc[1][0] += p1*vv.x; oacc[1][1] += p1*vv.y; oacc[1][2] += p1*vv.z; oacc[1][3] += p1*vv.w;
                oacc[2][0] += p2*vv.x; oacc[2][1] += p2*vv.y; oacc[2][2] += p2*vv.z; oacc[2][3] += p2*vv.w;
                oacc[3][0] += p3*vv.x; oacc[3][1] += p3*vv.y; oacc[3][2] += p3*vv.z; oacc[3][3] += p3*vv.w;
            }
        }
        __syncthreads();
    }

    // Normalize + write to [b,n,h*64+d]
    #pragma unroll
    for (int i = 0; i < 4; i++) {
        float linv = 1.f / l_s[tm + i];
        float4 o = make_float4(oacc[i][0]*linv, oacc[i][1]*linv, oacc[i][2]*linv, oacc[i][3]*linv);
        *(float4*)(g_ao + (size_t)(b*SEQ + q0 + tm + i) * DIMC + h*HD + tnD) = o;
    }
}

// ---------------------------------------------------------------------------
// Host: pure kernel launches, zero other runtime API calls.
// ---------------------------------------------------------------------------
extern "C" void kernel_launch(void* const* d_in, const int* in_sizes, int n_in,
                              void* d_out, int out_size)
{
    const float* x     = (const float*)d_in[0];
    const float* Wq    = (const float*)d_in[1];
    const float* Wkv   = (const float*)d_in[2];
    const float* Wproj = (const float*)d_in[3];
    const float* bproj = (const float*)d_in[4];
    float* out = (float*)d_out;

    // Q|KV = x @ [Wq;Wkv]^T  -> g_q, g_kv
    qkv_gemm<<<dim3(QKVN/64, ROWS/64), 256>>>(x, Wq, Wkv);
    // Attention -> g_ao
    attn_kernel<<<dim3(SEQ/64, NH, BATCH), 256>>>();
    // out = g_ao @ Wproj^T + bproj
    proj_gemm<<<dim3(DIMC/64, ROWS/64), 256>>>(Wproj, bproj, out);
}

// round 4
// speedup vs baseline: 1.5842x; 1.5842x over previous
#include <cuda_runtime.h>
#include <math.h>
#include <stdint.h>

#define DIMC   1024
#define NH     16
#define NKV    4
#define GROUPS 4
#define HD     64
#define SEQ    2048
#define BATCH  2
#define ROWS   (BATCH*SEQ)      /* 4096 */
#define KVC    (2*NKV*HD)       /* 512  */
#define QKVN   (DIMC + KVC)     /* 1536 */
#define SCALE  0.125f           /* 64^-0.5 */

// Scratch (allocation-free rule: __device__ globals)
__device__ float g_q [ROWS*DIMC];   // Q  [4096,1024]
__device__ float g_kv[ROWS*KVC];    // KV [4096,512] : k at +kvh*64, v at +256+kvh*64
__device__ float g_ao[ROWS*DIMC];   // attention output [4096,1024]

// ---------------------------------------------------------------------------
// mma.sync m16n8k8 tf32 helpers
// ---------------------------------------------------------------------------
__device__ __forceinline__ uint32_t f2tf(float f) {
    uint32_t r;
    asm("cvt.rna.tf32.f32 %0, %1;" : "=r"(r) : "f"(f));
    return r;
}
__device__ __forceinline__ void split_tf32(float a, uint32_t& hi, uint32_t& lo) {
    asm("cvt.rna.tf32.f32 %0, %1;" : "=r"(hi) : "f"(a));
    float ah = __uint_as_float(hi);
    asm("cvt.rna.tf32.f32 %0, %1;" : "=r"(lo) : "f"(a - ah));
}
__device__ __forceinline__ void mma8(float* c, const uint32_t* a, const uint32_t* b) {
    asm volatile(
        "mma.sync.aligned.m16n8k8.row.col.f32.tf32.tf32.f32 "
        "{%0,%1,%2,%3}, {%4,%5,%6,%7}, {%8,%9}, {%0,%1,%2,%3};"
        : "+f"(c[0]), "+f"(c[1]), "+f"(c[2]), "+f"(c[3])
        : "r"(a[0]), "r"(a[1]), "r"(a[2]), "r"(a[3]), "r"(b[0]), "r"(b[1]));
}

// ---------------------------------------------------------------------------
// 3xTF32 GEMM body: C[128 x 64 tile] = A[M,K] @ Bw[N,K]^T (+bias)
// 8 warps (4m x 2n), warp tile 32x32 (2 m-tiles x 4 n-tiles of m16n8).
// smem stride 36: fragment gather bank = (4*g + tg) % 32 == lane -> conflict-free.
// ---------------------------------------------------------------------------
__device__ __forceinline__ void gemm_mma_body(
    const float* __restrict__ A, const float* __restrict__ Bw,
    const float* __restrict__ bias, float* __restrict__ C,
    int ldc, int K, int m0, int nb)
{
    __shared__ float As[128*36];
    __shared__ float Bs[64*36];

    const int tid  = threadIdx.x;
    const int lane = tid & 31;
    const int warp = tid >> 5;
    const int wm   = warp >> 1;     // 0..3
    const int wn   = warp & 1;      // 0..1
    const int g    = lane >> 2;     // 0..7
    const int tg   = lane & 3;      // 0..3

    float acc[2][4][4] = {};

    for (int k0 = 0; k0 < K; k0 += 32) {
        #pragma unroll
        for (int i = 0; i < 4; i++) {             // A: 128x32
            int f = tid + i*256;                  // float4 id 0..1023
            int r = f >> 3, c = (f & 7) << 2;
            *(float4*)&As[r*36 + c] = *(const float4*)(A + (size_t)(m0 + r)*K + k0 + c);
        }
        #pragma unroll
        for (int i = 0; i < 2; i++) {             // B: 64x32
            int f = tid + i*256;                  // 0..511
            int r = f >> 3, c = (f & 7) << 2;
            *(float4*)&Bs[r*36 + c] = *(const float4*)(Bw + (size_t)(nb + r)*K + k0 + c);
        }
        __syncthreads();

        #pragma unroll
        for (int ks = 0; ks < 4; ks++) {
            const int kk = ks * 8;
            uint32_t ahi[2][4], alo[2][4];
            #pragma unroll
            for (int mt = 0; mt < 2; mt++) {
                const float* ab = &As[(wm*32 + mt*16)*36 + kk];
                split_tf32(ab[g*36 + tg],       ahi[mt][0], alo[mt][0]);
                split_tf32(ab[(g+8)*36 + tg],   ahi[mt][1], alo[mt][1]);
                split_tf32(ab[g*36 + tg+4],     ahi[mt][2], alo[mt][2]);
                split_tf32(ab[(g+8)*36 + tg+4], ahi[mt][3], alo[mt][3]);
            }
            uint32_t bhi[4][2], blo[4][2];
            #pragma unroll
            for (int nt = 0; nt < 4; nt++) {
                const float* bb = &Bs[(wn*32 + nt*8)*36 + kk];
                split_tf32(bb[g*36 + tg],   bhi[nt][0], blo[nt][0]);
                split_tf32(bb[g*36 + tg+4], bhi[nt][1], blo[nt][1]);
            }
            #pragma unroll
            for (int mt = 0; mt < 2; mt++)
                #pragma unroll
                for (int nt = 0; nt < 4; nt++) {
                    mma8(acc[mt][nt], ahi[mt], bhi[nt]);
                    mma8(acc[mt][nt], ahi[mt], blo[nt]);
                    mma8(acc[mt][nt], alo[mt], bhi[nt]);
                }
        }
        __syncthreads();
    }

    #pragma unroll
    for (int mt = 0; mt < 2; mt++) {
        int r0 = m0 + wm*32 + mt*16 + g;
        #pragma unroll
        for (int nt = 0; nt < 4; nt++) {
            int col = nb + wn*32 + nt*8 + 2*tg;
            float b0 = 0.f, b1 = 0.f;
            if (bias) { b0 = bias[col]; b1 = bias[col+1]; }
            *(float2*)(C + (size_t)r0*ldc + col) =
                make_float2(acc[mt][nt][0] + b0, acc[mt][nt][1] + b1);
            *(float2*)(C + (size_t)(r0+8)*ldc + col) =
                make_float2(acc[mt][nt][2] + b0, acc[mt][nt][3] + b1);
        }
    }
}

// Fused QKV projection: block col < 1024 -> Q, else KV
__global__ void __launch_bounds__(256) qkv_gemm(
    const float* __restrict__ x, const float* __restrict__ Wq,
    const float* __restrict__ Wkv)
{
    const int m0 = blockIdx.y * 128;
    const int n0 = blockIdx.x * 64;
    if (n0 < DIMC) gemm_mma_body(x, Wq,  nullptr, g_q,  DIMC, DIMC, m0, n0);
    else           gemm_mma_body(x, Wkv, nullptr, g_kv, KVC,  DIMC, m0, n0 - DIMC);
}

__global__ void __launch_bounds__(256) proj_gemm(
    const float* __restrict__ Wproj, const float* __restrict__ bproj,
    float* __restrict__ out)
{
    gemm_mma_body(g_ao, Wproj, bproj, out, DIMC, DIMC, blockIdx.y * 128, blockIdx.x * 64);
}

// ---------------------------------------------------------------------------
// Flash attention: 64 Q rows/CTA, j-tile 32, tensor-core S and PV.
// S = QK^T via 3xTF32 (exact-ish), PV single-pass tf32. Softmax fp32.
// Static smem 45.3KB.
// ---------------------------------------------------------------------------
__global__ void __launch_bounds__(256) attn_kernel()
{
    __shared__ float Qs[64*68];     // [r][d]  17408 B
    __shared__ float Ks[32*68];     // [j][d]   8704 B
    __shared__ float Vs[32*72];     // [j][d]   9216 B
    __shared__ float Ss[64*36];     // [r][j]   9216 B
    __shared__ float m_s[64], l_s[64], a_s[64];

    const int tid  = threadIdx.x;
    const int lane = tid & 31;
    const int warp = tid >> 5;
    const int wm   = warp >> 1;     // 0..3  (16 rows each)
    const int wn   = warp & 1;      // 0..1
    const int g    = lane >> 2;
    const int tg   = lane & 3;

    const int q0  = blockIdx.x * 64;
    const int h   = blockIdx.y;
    const int b   = blockIdx.z;
    const int kvh = h >> 2;

    const int r  = tid >> 2;        // softmax row
    const int jq = tid & 3;         // softmax eighth

    // Load Q tile [64][64], pre-scaled
    #pragma unroll
    for (int i = 0; i < 4; i++) {
        int f = tid + i*256;        // 0..1023
        int rr = f >> 4, c = (f & 15) << 2;
        float4 q = *(const float4*)(g_q + (size_t)(b*SEQ + q0 + rr)*DIMC + h*HD + c);
        q.x *= SCALE; q.y *= SCALE; q.z *= SCALE; q.w *= SCALE;
        *(float4*)&Qs[rr*68 + c] = q;
    }
    if (tid < 64) { m_s[tid] = -INFINITY; l_s[tid] = 0.f; }

    float oacc[4][4] = {};          // [nt][c-reg], warp: 16 rows x 32 d
    __syncthreads();

    for (int j0 = 0; j0 < SEQ; j0 += 32) {
        // Load K,V (32 rows x 64 d each)
        #pragma unroll
        for (int i = 0; i < 2; i++) {
            int f = tid + i*256;    // 0..511
            int rr = f >> 4, c = (f & 15) << 2;
            const float* kvb = g_kv + (size_t)(b*SEQ + j0 + rr)*KVC + kvh*HD;
            *(float4*)&Ks[rr*68 + c] = *(const float4*)(kvb + c);
            *(float4*)&Vs[rr*72 + c] = *(const float4*)(kvb + 256 + c);
        }
        __syncthreads();

        // S = Q K^T : warp tile 16 rows x 16 j-cols, 3xTF32
        float sacc[2][4] = {};
        #pragma unroll
        for (int ks = 0; ks < 8; ks++) {
            const int kk = ks * 8;
            uint32_t qhi[4], qlo[4];
            const float* qb = &Qs[(wm*16)*68 + kk];
            split_tf32(qb[g*68 + tg],       qhi[0], qlo[0]);
            split_tf32(qb[(g+8)*68 + tg],   qhi[1], qlo[1]);
            split_tf32(qb[g*68 + tg+4],     qhi[2], qlo[2]);
            split_tf32(qb[(g+8)*68 + tg+4], qhi[3], qlo[3]);
            #pragma unroll
            for (int nt = 0; nt < 2; nt++) {
                const float* kb = &Ks[(wn*16 + nt*8)*68 + kk];
                uint32_t khi[2], klo[2];
                split_tf32(kb[g*68 + tg],   khi[0], klo[0]);
                split_tf32(kb[g*68 + tg+4], khi[1], klo[1]);
                mma8(sacc[nt], qhi, khi);
                mma8(sacc[nt], qhi, klo);
                mma8(sacc[nt], qlo, khi);
            }
        }
        #pragma unroll
        for (int nt = 0; nt < 2; nt++) {
            int col = wn*16 + nt*8 + 2*tg;
            *(float2*)&Ss[(wm*16 + g)*36 + col]     = make_float2(sacc[nt][0], sacc[nt][1]);
            *(float2*)&Ss[(wm*16 + g + 8)*36 + col] = make_float2(sacc[nt][2], sacc[nt][3]);
        }
        __syncthreads();

        // Online softmax (fp32): 4 threads/row, 8 cols each
        {
            float* prow = &Ss[r*36 + jq*8];
            float mx = -INFINITY;
            #pragma unroll
            for (int j = 0; j < 8; j++) mx = fmaxf(mx, prow[j]);
            mx = fmaxf(mx, __shfl_xor_sync(0xffffffffu, mx, 1));
            mx = fmaxf(mx, __shfl_xor_sync(0xffffffffu, mx, 2));
            float mold = m_s[r];
            float mnew = fmaxf(mold, mx);
            float lsum = 0.f;
            #pragma unroll
            for (int j = 0; j < 8; j++) {
                float p = __expf(prow[j] - mnew);
                prow[j] = p;
                lsum += p;
            }
            lsum += __shfl_xor_sync(0xffffffffu, lsum, 1);
            lsum += __shfl_xor_sync(0xffffffffu, lsum, 2);
            if (jq == 0) {
                float alpha = __expf(mold - mnew);
                l_s[r] = l_s[r] * alpha + lsum;
                m_s[r] = mnew;
                a_s[r] = alpha;
            }
        }
        __syncthreads();

        // O = O*alpha + P V : warp tile 16 rows x 32 d, single-pass tf32
        {
            float al0 = a_s[wm*16 + g];
            float al1 = a_s[wm*16 + g + 8];
            #pragma unroll
            for (int nt = 0; nt < 4; nt++) {
                oacc[nt][0] *= al0; oacc[nt][1] *= al0;
                oacc[nt][2] *= al1; oacc[nt][3] *= al1;
            }
            #pragma unroll
            for (int ks = 0; ks < 4; ks++) {
                const int kk = ks * 8;
                uint32_t a[4];
                const float* pb = &Ss[(wm*16)*36 + kk];
                a[0] = f2tf(pb[g*36 + tg]);
                a[1] = f2tf(pb[(g+8)*36 + tg]);
                a[2] = f2tf(pb[g*36 + tg+4]);
                a[3] = f2tf(pb[(g+8)*36 + tg+4]);
                #pragma unroll
                for (int nt = 0; nt < 4; nt++) {
                    const float* vb = &Vs[kk*72 + wn*32 + nt*8];
                    uint32_t bv[2];
                    bv[0] = f2tf(vb[tg*72 + g]);
                    bv[1] = f2tf(vb[(tg+4)*72 + g]);
                    mma8(oacc[nt], a, bv);
                }
            }
        }
        __syncthreads();
    }

    // Normalize + store
    {
        float li0 = 1.f / l_s[wm*16 + g];
        float li1 = 1.f / l_s[wm*16 + g + 8];
        float* o0 = g_ao + (size_t)(b*SEQ + q0 + wm*16 + g)*DIMC + h*HD;
        float* o1 = g_ao + (size_t)(b*SEQ + q0 + wm*16 + g + 8)*DIMC + h*HD;
        #pragma unroll
        for (int nt = 0; nt < 4; nt++) {
            int col = wn*32 + nt*8 + 2*tg;
            *(float2*)(o0 + col) = make_float2(oacc[nt][0]*li0, oacc[nt][1]*li0);
            *(float2*)(o1 + col) = make_float2(oacc[nt][2]*li1, oacc[nt][3]*li1);
        }
    }
}

// ---------------------------------------------------------------------------
// Host: pure kernel launches only.
// ---------------------------------------------------------------------------
extern "C" void kernel_launch(void* const* d_in, const int* in_sizes, int n_in,
                              void* d_out, int out_size)
{
    const float* x     = (const float*)d_in[0];
    const float* Wq    = (const float*)d_in[1];
    const float* Wkv   = (const float*)d_in[2];
    const float* Wproj = (const float*)d_in[3];
    const float* bproj = (const float*)d_in[4];
    float* out = (float*)d_out;

    qkv_gemm<<<dim3(QKVN/64, ROWS/128), 256>>>(x, Wq, Wkv);
    attn_kernel<<<dim3(SEQ/64, NH, BATCH), 256>>>();
    proj_gemm<<<dim3(DIMC/64, ROWS/128), 256>>>(Wproj, bproj, out);
}

// round 5
// speedup vs baseline: 1.8395x; 1.1611x over previous
#include <cuda_runtime.h>
#include <math.h>
#include <stdint.h>

#define DIMC   1024
#define NH     16
#define NKV    4
#define GROUPS 4
#define HD     64
#define SEQ    2048
#define BATCH  2
#define ROWS   (BATCH*SEQ)      /* 4096 */
#define KVC    (2*NKV*HD)       /* 512  */
#define QKVN   (DIMC + KVC)     /* 1536 */
#define SCALE  0.125f           /* 64^-0.5 */

// Scratch (allocation-free rule: __device__ globals)
__device__ float g_q [ROWS*DIMC];   // Q  [4096,1024]
__device__ float g_kv[ROWS*KVC];    // KV [4096,512] : k at +kvh*64, v at +256+kvh*64
__device__ float g_ao[ROWS*DIMC];   // attention output [4096,1024]

// ---------------------------------------------------------------------------
// tf32 helpers
// ---------------------------------------------------------------------------
__device__ __forceinline__ uint32_t f2tf(float f) {
    uint32_t r;
    asm("cvt.rna.tf32.f32 %0, %1;" : "=r"(r) : "f"(f));
    return r;
}
__device__ __forceinline__ void split_tf32(float a, uint32_t& hi, uint32_t& lo) {
    asm("cvt.rna.tf32.f32 %0, %1;" : "=r"(hi) : "f"(a));
    float ah = __uint_as_float(hi);
    asm("cvt.rna.tf32.f32 %0, %1;" : "=r"(lo) : "f"(a - ah));
}
__device__ __forceinline__ void mma8(float* c, const uint32_t* a, const uint32_t* b) {
    asm volatile(
        "mma.sync.aligned.m16n8k8.row.col.f32.tf32.tf32.f32 "
        "{%0,%1,%2,%3}, {%4,%5,%6,%7}, {%8,%9}, {%0,%1,%2,%3};"
        : "+f"(c[0]), "+f"(c[1]), "+f"(c[2]), "+f"(c[3])
        : "r"(a[0]), "r"(a[1]), "r"(a[2]), "r"(a[3]), "r"(b[0]), "r"(b[1]));
}
__device__ __forceinline__ float4 split4_hi(float4 a, float4& lo) {
    uint32_t h0,l0,h1,l1,h2,l2,h3,l3;
    split_tf32(a.x,h0,l0); split_tf32(a.y,h1,l1);
    split_tf32(a.z,h2,l2); split_tf32(a.w,h3,l3);
    lo = make_float4(__uint_as_float(l0),__uint_as_float(l1),
                     __uint_as_float(l2),__uint_as_float(l3));
    return make_float4(__uint_as_float(h0),__uint_as_float(h1),
                       __uint_as_float(h2),__uint_as_float(h3));
}

// ---------------------------------------------------------------------------
// 3xTF32 GEMM: C[128x128 tile] = A[M,K] @ Bw[N,K]^T (+bias)
// Pre-split hi/lo tiles in smem (k-tile 16, stride 20 -> conflict-free gathers:
// bank(g*20+tg) over lanes covers all 32 banks). Warp grid 2x4, tile 64x32.
// ---------------------------------------------------------------------------
__device__ __forceinline__ void gemm_mma_body(
    const float* __restrict__ A, const float* __restrict__ Bw,
    const float* __restrict__ bias, float* __restrict__ C,
    int ldc, int K, int m0, int nb)
{
    __shared__ float Ahi[128*20], Alo[128*20];
    __shared__ float Bhi[128*20], Blo[128*20];

    const int tid  = threadIdx.x;
    const int lane = tid & 31;
    const int warp = tid >> 5;
    const int wm   = warp >> 2;     // 0..1  (64 rows)
    const int wn   = warp & 3;      // 0..3  (32 cols)
    const int g    = lane >> 2;
    const int tg   = lane & 3;

    float acc[4][4][4] = {};        // [mt][nt][reg]

    for (int k0 = 0; k0 < K; k0 += 16) {
        #pragma unroll
        for (int i = 0; i < 2; i++) {
            int f = tid + i*256;            // 0..511 float4 slots (128 rows x 4)
            int r = f >> 2, c = (f & 3) << 2;
            float4 lo, hi;
            hi = split4_hi(*(const float4*)(A + (size_t)(m0 + r)*K + k0 + c), lo);
            *(float4*)&Ahi[r*20 + c] = hi;
            *(float4*)&Alo[r*20 + c] = lo;
            hi = split4_hi(*(const float4*)(Bw + (size_t)(nb + r)*K + k0 + c), lo);
            *(float4*)&Bhi[r*20 + c] = hi;
            *(float4*)&Blo[r*20 + c] = lo;
        }
        __syncthreads();

        #pragma unroll
        for (int ks = 0; ks < 2; ks++) {
            const int kk = ks * 8;
            uint32_t ah[4][4], al[4][4];
            #pragma unroll
            for (int mt = 0; mt < 4; mt++) {
                const float* ph = &Ahi[(wm*64 + mt*16)*20 + kk];
                const float* pl = &Alo[(wm*64 + mt*16)*20 + kk];
                ah[mt][0] = __float_as_uint(ph[g*20 + tg]);
                ah[mt][1] = __float_as_uint(ph[(g+8)*20 + tg]);
                ah[mt][2] = __float_as_uint(ph[g*20 + tg+4]);
                ah[mt][3] = __float_as_uint(ph[(g+8)*20 + tg+4]);
                al[mt][0] = __float_as_uint(pl[g*20 + tg]);
                al[mt][1] = __float_as_uint(pl[(g+8)*20 + tg]);
                al[mt][2] = __float_as_uint(pl[g*20 + tg+4]);
                al[mt][3] = __float_as_uint(pl[(g+8)*20 + tg+4]);
            }
            uint32_t bh[4][2], bl[4][2];
            #pragma unroll
            for (int nt = 0; nt < 4; nt++) {
                const float* ph = &Bhi[(wn*32 + nt*8)*20 + kk];
                const float* pl = &Blo[(wn*32 + nt*8)*20 + kk];
                bh[nt][0] = __float_as_uint(ph[g*20 + tg]);
                bh[nt][1] = __float_as_uint(ph[g*20 + tg+4]);
                bl[nt][0] = __float_as_uint(pl[g*20 + tg]);
                bl[nt][1] = __float_as_uint(pl[g*20 + tg+4]);
            }
            #pragma unroll
            for (int mt = 0; mt < 4; mt++)
                #pragma unroll
                for (int nt = 0; nt < 4; nt++) {
                    mma8(acc[mt][nt], ah[mt], bh[nt]);
                    mma8(acc[mt][nt], ah[mt], bl[nt]);
                    mma8(acc[mt][nt], al[mt], bh[nt]);
                }
        }
        __syncthreads();
    }

    #pragma unroll
    for (int mt = 0; mt < 4; mt++) {
        int r0 = m0 + wm*64 + mt*16 + g;
        #pragma unroll
        for (int nt = 0; nt < 4; nt++) {
            int col = nb + wn*32 + nt*8 + 2*tg;
            float b0 = 0.f, b1 = 0.f;
            if (bias) { b0 = bias[col]; b1 = bias[col+1]; }
            *(float2*)(C + (size_t)r0*ldc + col) =
                make_float2(acc[mt][nt][0] + b0, acc[mt][nt][1] + b1);
            *(float2*)(C + (size_t)(r0+8)*ldc + col) =
                make_float2(acc[mt][nt][2] + b0, acc[mt][nt][3] + b1);
        }
    }
}

__global__ void __launch_bounds__(256) qkv_gemm(
    const float* __restrict__ x, const float* __restrict__ Wq,
    const float* __restrict__ Wkv)
{
    const int m0 = blockIdx.y * 128;
    const int n0 = blockIdx.x * 128;
    if (n0 < DIMC) gemm_mma_body(x, Wq,  nullptr, g_q,  DIMC, DIMC, m0, n0);
    else           gemm_mma_body(x, Wkv, nullptr, g_kv, KVC,  DIMC, m0, n0 - DIMC);
}

__global__ void __launch_bounds__(256) proj_gemm(
    const float* __restrict__ Wproj, const float* __restrict__ bproj,
    float* __restrict__ out)
{
    gemm_mma_body(g_ao, Wproj, bproj, out, DIMC, DIMC, blockIdx.y * 128, blockIdx.x * 128);
}

// ---------------------------------------------------------------------------
// Flash attention: 64 Q rows/CTA, j-tile 32, all conversions hoisted.
// Q split to registers once; K split at load; V tf32 at load; P stored as tf32.
// Smem pool reused: phase0 Qs(64x68) -> phase1 Khi/Klo(32x68) Vs(32x72) Ss(64x36).
// ---------------------------------------------------------------------------
__global__ void __launch_bounds__(256) attn_kernel()
{
    __shared__ float pool[8960];    // 35840 B
    __shared__ float m_s[64], l_s[64], a_s[64];
    float* Qs  = pool;              // 64*68 = 4352
    float* Khi = pool;              // 32*68 = 2176
    float* Klo = pool + 2176;
    float* Vs  = pool + 4352;       // 32*72 = 2304
    float* Ss  = pool + 6656;       // 64*36 = 2304

    const int tid  = threadIdx.x;
    const int lane = tid & 31;
    const int warp = tid >> 5;
    const int wm   = warp >> 1;     // 0..3 (16 rows)
    const int wn   = warp & 1;      // 0..1
    const int g    = lane >> 2;
    const int tg   = lane & 3;

    const int q0  = blockIdx.x * 64;
    const int h   = blockIdx.y;
    const int b   = blockIdx.z;
    const int kvh = h >> 2;

    const int r  = tid >> 2;
    const int jq = tid & 3;

    // Phase 0: load Q (scaled) to smem
    #pragma unroll
    for (int i = 0; i < 4; i++) {
        int f = tid + i*256, rr = f >> 4, c = (f & 15) << 2;
        float4 q = *(const float4*)(g_q + (size_t)(b*SEQ + q0 + rr)*DIMC + h*HD + c);
        q.x *= SCALE; q.y *= SCALE; q.z *= SCALE; q.w *= SCALE;
        *(float4*)&Qs[rr*68 + c] = q;
    }
    if (tid < 64) { m_s[tid] = -INFINITY; l_s[tid] = 0.f; }
    __syncthreads();

    // Split Q fragments into registers (fixed for all j)
    uint32_t qhi[8][4], qlo[8][4];
    #pragma unroll
    for (int ks = 0; ks < 8; ks++) {
        const float* qb = &Qs[(wm*16)*68 + ks*8];
        split_tf32(qb[g*68 + tg],       qhi[ks][0], qlo[ks][0]);
        split_tf32(qb[(g+8)*68 + tg],   qhi[ks][1], qlo[ks][1]);
        split_tf32(qb[g*68 + tg+4],     qhi[ks][2], qlo[ks][2]);
        split_tf32(qb[(g+8)*68 + tg+4], qhi[ks][3], qlo[ks][3]);
    }
    float oacc[4][4] = {};
    __syncthreads();                 // Qs space now reusable

    for (int j0 = 0; j0 < SEQ; j0 += 32) {
        // Load K (split hi/lo) and V (tf32) : 32 rows x 64 d
        #pragma unroll
        for (int i = 0; i < 2; i++) {
            int f = tid + i*256, rr = f >> 4, c = (f & 15) << 2;
            const float* kvb = g_kv + (size_t)(b*SEQ + j0 + rr)*KVC + kvh*HD;
            float4 lo, hi;
            hi = split4_hi(*(const float4*)(kvb + c), lo);
            *(float4*)&Khi[rr*68 + c] = hi;
            *(float4*)&Klo[rr*68 + c] = lo;
            float4 vv = *(const float4*)(kvb + 256 + c);
            *(float4*)&Vs[rr*72 + c] = make_float4(
                __uint_as_float(f2tf(vv.x)), __uint_as_float(f2tf(vv.y)),
                __uint_as_float(f2tf(vv.z)), __uint_as_float(f2tf(vv.w)));
        }
        __syncthreads();

        // S = Q K^T (3xTF32): warp tile 16 x 16
        float sacc[2][4] = {};
        #pragma unroll
        for (int ks = 0; ks < 8; ks++) {
            const int kk = ks * 8;
            #pragma unroll
            for (int nt = 0; nt < 2; nt++) {
                const float* ph = &Khi[(wn*16 + nt*8)*68 + kk];
                const float* pl = &Klo[(wn*16 + nt*8)*68 + kk];
                uint32_t kh[2] = { __float_as_uint(ph[g*68 + tg]),
                                   __float_as_uint(ph[g*68 + tg+4]) };
                uint32_t kl[2] = { __float_as_uint(pl[g*68 + tg]),
                                   __float_as_uint(pl[g*68 + tg+4]) };
                mma8(sacc[nt], qhi[ks], kh);
                mma8(sacc[nt], qhi[ks], kl);
                mma8(sacc[nt], qlo[ks], kh);
            }
        }
        #pragma unroll
        for (int nt = 0; nt < 2; nt++) {
            int col = wn*16 + nt*8 + 2*tg;
            *(float2*)&Ss[(wm*16 + g)*36 + col]     = make_float2(sacc[nt][0], sacc[nt][1]);
            *(float2*)&Ss[(wm*16 + g + 8)*36 + col] = make_float2(sacc[nt][2], sacc[nt][3]);
        }
        __syncthreads();

        // Online softmax (fp32 stats; stores tf32(p) bit patterns into Ss)
        {
            float* prow = &Ss[r*36 + jq*8];
            float mx = -INFINITY;
            #pragma unroll
            for (int j = 0; j < 8; j++) mx = fmaxf(mx, prow[j]);
            mx = fmaxf(mx, __shfl_xor_sync(0xffffffffu, mx, 1));
            mx = fmaxf(mx, __shfl_xor_sync(0xffffffffu, mx, 2));
            float mold = m_s[r];
            float mnew = fmaxf(mold, mx);
            float lsum = 0.f;
            #pragma unroll
            for (int j = 0; j < 8; j++) {
                float p = __expf(prow[j] - mnew);
                lsum += p;
                prow[j] = __uint_as_float(f2tf(p));
            }
            lsum += __shfl_xor_sync(0xffffffffu, lsum, 1);
            lsum += __shfl_xor_sync(0xffffffffu, lsum, 2);
            if (jq == 0) {
                float alpha = __expf(mold - mnew);
                l_s[r] = l_s[r] * alpha + lsum;
                m_s[r] = mnew;
                a_s[r] = alpha;
            }
        }
        __syncthreads();

        // O = O*alpha + P V : warp tile 16 x 32, pure LDS+MMA
        {
            float al0 = a_s[wm*16 + g];
            float al1 = a_s[wm*16 + g + 8];
            #pragma unroll
            for (int nt = 0; nt < 4; nt++) {
                oacc[nt][0] *= al0; oacc[nt][1] *= al0;
                oacc[nt][2] *= al1; oacc[nt][3] *= al1;
            }
            #pragma unroll
            for (int ks = 0; ks < 4; ks++) {
                const int kk = ks * 8;
                const float* pb = &Ss[(wm*16)*36 + kk];
                uint32_t a[4] = {
                    __float_as_uint(pb[g*36 + tg]),
                    __float_as_uint(pb[(g+8)*36 + tg]),
                    __float_as_uint(pb[g*36 + tg+4]),
                    __float_as_uint(pb[(g+8)*36 + tg+4]) };
                #pragma unroll
                for (int nt = 0; nt < 4; nt++) {
                    const float* vb = &Vs[kk*72 + wn*32 + nt*8];
                    uint32_t bv[2] = {
                        __float_as_uint(vb[tg*72 + g]),
                        __float_as_uint(vb[(tg+4)*72 + g]) };
                    mma8(oacc[nt], a, bv);
                }
            }
        }
        __syncthreads();
    }

    // Normalize + store
    {
        float li0 = 1.f / l_s[wm*16 + g];
        float li1 = 1.f / l_s[wm*16 + g + 8];
        float* o0 = g_ao + (size_t)(b*SEQ + q0 + wm*16 + g)*DIMC + h*HD;
        float* o1 = g_ao + (size_t)(b*SEQ + q0 + wm*16 + g + 8)*DIMC + h*HD;
        #pragma unroll
        for (int nt = 0; nt < 4; nt++) {
            int col = wn*32 + nt*8 + 2*tg;
            *(float2*)(o0 + col) = make_float2(oacc[nt][0]*li0, oacc[nt][1]*li0);
            *(float2*)(o1 + col) = make_float2(oacc[nt][2]*li1, oacc[nt][3]*li1);
        }
    }
}

// ---------------------------------------------------------------------------
extern "C" void kernel_launch(void* const* d_in, const int* in_sizes, int n_in,
                              void* d_out, int out_size)
{
    const float* x     = (const float*)d_in[0];
    const float* Wq    = (const float*)d_in[1];
    const float* Wkv   = (const float*)d_in[2];
    const float* Wproj = (const float*)d_in[3];
    const float* bproj = (const float*)d_in[4];
    float* out = (float*)d_out;

    qkv_gemm<<<dim3(QKVN/128, ROWS/128), 256>>>(x, Wq, Wkv);
    attn_kernel<<<dim3(SEQ/64, NH, BATCH), 256>>>();
    proj_gemm<<<dim3(DIMC/128, ROWS/128), 256>>>(Wproj, bproj, out);
}

// round 6
// speedup vs baseline: 2.4632x; 1.3390x over previous
#include <cuda_runtime.h>
#include <cuda_bf16.h>
#include <math.h>
#include <stdint.h>

#define DIMC   1024
#define NH     16
#define NKV    4
#define GROUPS 4
#define HD     64
#define SEQ    2048
#define BATCH  2
#define ROWS   (BATCH*SEQ)      /* 4096 */
#define KVC    (2*NKV*HD)       /* 512  */
#define QKVN   (DIMC + KVC)     /* 1536 */
#define SCALE  0.125f           /* 64^-0.5 */

// Scratch (allocation-free rule: __device__ globals)
__device__ float g_q [ROWS*DIMC];
__device__ float g_kv[ROWS*KVC];    // k at +kvh*64, v at +256+kvh*64
__device__ float g_ao[ROWS*DIMC];

// ---------------------------------------------------------------------------
// bf16 helpers: split fp32 pair -> packed bf16x2 (hi) + packed bf16x2 (lo)
// ---------------------------------------------------------------------------
__device__ __forceinline__ void split2(float x, float y, uint32_t& hi, uint32_t& lo) {
    __nv_bfloat162 h = __floats2bfloat162_rn(x, y);
    float hx = __bfloat162float(__low2bfloat16(h));
    float hy = __bfloat162float(__high2bfloat16(h));
    __nv_bfloat162 l = __floats2bfloat162_rn(x - hx, y - hy);
    hi = *(uint32_t*)&h;
    lo = *(uint32_t*)&l;
}
__device__ __forceinline__ void mma16(float* c, const uint32_t* a, const uint32_t* b) {
    asm volatile(
        "mma.sync.aligned.m16n8k16.row.col.f32.bf16.bf16.f32 "
        "{%0,%1,%2,%3}, {%4,%5,%6,%7}, {%8,%9}, {%0,%1,%2,%3};"
        : "+f"(c[0]), "+f"(c[1]), "+f"(c[2]), "+f"(c[3])
        : "r"(a[0]), "r"(a[1]), "r"(a[2]), "r"(a[3]), "r"(b[0]), "r"(b[1]));
}

// ---------------------------------------------------------------------------
// bf16-split GEMM: C[128x128 tile] = A[M,K] @ Bw[N,K]^T (+bias)
// smem: packed bf16x2 hi/lo tiles, k-tile 32 (16 pairs, stride 20 u32).
// 8 warps (2m x 4n), warp tile 64x32. 3 mma per (mt,nt,k16).
// ---------------------------------------------------------------------------
__device__ __forceinline__ void gemm_mma_body(
    const float* __restrict__ A, const float* __restrict__ Bw,
    const float* __restrict__ bias, float* __restrict__ C,
    int ldc, int K, int m0, int nb)
{
    __shared__ uint32_t Ahi[128*20], Alo[128*20];
    __shared__ uint32_t Bhi[128*20], Blo[128*20];

    const int tid  = threadIdx.x;
    const int lane = tid & 31;
    const int warp = tid >> 5;
    const int wm   = warp >> 2;     // 0..1 (64 rows)
    const int wn   = warp & 3;      // 0..3 (32 cols)
    const int g    = lane >> 2;
    const int tg   = lane & 3;

    float acc[4][4][4] = {};

    for (int k0 = 0; k0 < K; k0 += 32) {
        #pragma unroll
        for (int i = 0; i < 4; i++) {              // A: 128x32 -> 1024 float4
            int f = tid + i*256;
            int r = f >> 3, c = (f & 7) << 2;      // c: 0..28
            float4 a = *(const float4*)(A + (size_t)(m0 + r)*K + k0 + c);
            uint32_t h0,l0,h1,l1;
            split2(a.x, a.y, h0, l0); split2(a.z, a.w, h1, l1);
            *(uint2*)&Ahi[r*20 + (c>>1)] = make_uint2(h0, h1);
            *(uint2*)&Alo[r*20 + (c>>1)] = make_uint2(l0, l1);
        }
        #pragma unroll
        for (int i = 0; i < 4; i++) {              // B: 128x32
            int f = tid + i*256;
            int r = f >> 3, c = (f & 7) << 2;
            float4 b = *(const float4*)(Bw + (size_t)(nb + r)*K + k0 + c);
            uint32_t h0,l0,h1,l1;
            split2(b.x, b.y, h0, l0); split2(b.z, b.w, h1, l1);
            *(uint2*)&Bhi[r*20 + (c>>1)] = make_uint2(h0, h1);
            *(uint2*)&Blo[r*20 + (c>>1)] = make_uint2(l0, l1);
        }
        __syncthreads();

        #pragma unroll
        for (int ks = 0; ks < 2; ks++) {
            const int kb = ks * 8;                 // pair base
            uint32_t ah[4][4], al[4][4];
            #pragma unroll
            for (int mt = 0; mt < 4; mt++) {
                int r0 = (wm*64 + mt*16 + g)*20 + kb + tg;
                int r1 = r0 + 8*20;
                ah[mt][0] = Ahi[r0];   ah[mt][1] = Ahi[r1];
                ah[mt][2] = Ahi[r0+4]; ah[mt][3] = Ahi[r1+4];
                al[mt][0] = Alo[r0];   al[mt][1] = Alo[r1];
                al[mt][2] = Alo[r0+4]; al[mt][3] = Alo[r1+4];
            }
            uint32_t bh[4][2], bl[4][2];
            #pragma unroll
            for (int nt = 0; nt < 4; nt++) {
                int r0 = (wn*32 + nt*8 + g)*20 + kb + tg;
                bh[nt][0] = Bhi[r0]; bh[nt][1] = Bhi[r0+4];
                bl[nt][0] = Blo[r0]; bl[nt][1] = Blo[r0+4];
            }
            #pragma unroll
            for (int mt = 0; mt < 4; mt++)
                #pragma unroll
                for (int nt = 0; nt < 4; nt++) {
                    mma16(acc[mt][nt], ah[mt], bh[nt]);
                    mma16(acc[mt][nt], ah[mt], bl[nt]);
                    mma16(acc[mt][nt], al[mt], bh[nt]);
                }
        }
        __syncthreads();
    }

    #pragma unroll
    for (int mt = 0; mt < 4; mt++) {
        int r0 = m0 + wm*64 + mt*16 + g;
        #pragma unroll
        for (int nt = 0; nt < 4; nt++) {
            int col = nb + wn*32 + nt*8 + 2*tg;
            float b0 = 0.f, b1 = 0.f;
            if (bias) { b0 = bias[col]; b1 = bias[col+1]; }
            *(float2*)(C + (size_t)r0*ldc + col) =
                make_float2(acc[mt][nt][0] + b0, acc[mt][nt][1] + b1);
            *(float2*)(C + (size_t)(r0+8)*ldc + col) =
                make_float2(acc[mt][nt][2] + b0, acc[mt][nt][3] + b1);
        }
    }
}

__global__ void __launch_bounds__(256) qkv_gemm(
    const float* __restrict__ x, const float* __restrict__ Wq,
    const float* __restrict__ Wkv)
{
    const int m0 = blockIdx.y * 128;
    const int n0 = blockIdx.x * 128;
    if (n0 < DIMC) gemm_mma_body(x, Wq,  nullptr, g_q,  DIMC, DIMC, m0, n0);
    else           gemm_mma_body(x, Wkv, nullptr, g_kv, KVC,  DIMC, m0, n0 - DIMC);
}

__global__ void __launch_bounds__(256) proj_gemm(
    const float* __restrict__ Wproj, const float* __restrict__ bproj,
    float* __restrict__ out)
{
    gemm_mma_body(g_ao, Wproj, bproj, out, DIMC, DIMC, blockIdx.y * 128, blockIdx.x * 128);
}

// ---------------------------------------------------------------------------
// Flash attention, bf16-split mma. 64 Q rows/CTA, j-tile 32.
// Pool layout (u32): Khi[0,1152) Klo[1152,2304) Vph[2304,3456) Vpl[3456,4608)
//                    Ss(f32)[4608,6912) Psh[6912,8192) Psl[8192,9472)
// Phase 0 reuses [0,4352) as Qs (fp32).
// ---------------------------------------------------------------------------
__global__ void __launch_bounds__(256) attn_kernel()
{
    __shared__ uint32_t pool[9472];
    __shared__ float m_s[64], l_s[64], a_s[64];
    float*    Qs  = (float*)pool;       // 64*68 fp32
    uint32_t* Khi = pool;               // 32*36
    uint32_t* Klo = pool + 1152;
    uint32_t* Vph = pool + 2304;        // 16*72 (jpair-major, d cols)
    uint32_t* Vpl = pool + 3456;
    float*    Ss  = (float*)(pool + 4608);  // 64*36 fp32
    uint32_t* Psh = pool + 6912;        // 64*20 packed pairs
    uint32_t* Psl = pool + 8192;

    const int tid  = threadIdx.x;
    const int lane = tid & 31;
    const int warp = tid >> 5;
    const int wm   = warp >> 1;         // 0..3 (16 rows)
    const int wn   = warp & 1;          // 0..1
    const int g    = lane >> 2;
    const int tg   = lane & 3;

    const int q0  = blockIdx.x * 64;
    const int h   = blockIdx.y;
    const int b   = blockIdx.z;
    const int kvh = h >> 2;

    const int r  = tid >> 2;
    const int jq = tid & 3;

    // Phase 0: load Q (scaled) to smem
    #pragma unroll
    for (int i = 0; i < 4; i++) {
        int f = tid + i*256, rr = f >> 4, c = (f & 15) << 2;
        float4 q = *(const float4*)(g_q + (size_t)(b*SEQ + q0 + rr)*DIMC + h*HD + c);
        q.x *= SCALE; q.y *= SCALE; q.z *= SCALE; q.w *= SCALE;
        *(float4*)&Qs[rr*68 + c] = q;
    }
    if (tid < 64) { m_s[tid] = -INFINITY; l_s[tid] = 0.f; }
    __syncthreads();

    // Split Q fragments to registers: 4 k16-steps x 4 regs, hi+lo
    uint32_t qhi[4][4], qlo[4][4];
    #pragma unroll
    for (int ks = 0; ks < 4; ks++) {
        const int kb = ks*16;
        const float* q0p = &Qs[(wm*16 + g)*68 + kb];
        const float* q1p = &Qs[(wm*16 + g + 8)*68 + kb];
        split2(q0p[2*tg],   q0p[2*tg+1],   qhi[ks][0], qlo[ks][0]);
        split2(q1p[2*tg],   q1p[2*tg+1],   qhi[ks][1], qlo[ks][1]);
        split2(q0p[2*tg+8], q0p[2*tg+9],   qhi[ks][2], qlo[ks][2]);
        split2(q1p[2*tg+8], q1p[2*tg+9],   qhi[ks][3], qlo[ks][3]);
    }
    float oacc[4][4] = {};
    __syncthreads();                     // Qs region now reusable

    for (int j0 = 0; j0 < SEQ; j0 += 32) {
        // K loader: 32 rows x 64 d -> packed pairs [j][kpair], stride 36
        #pragma unroll
        for (int i = 0; i < 2; i++) {
            int f = tid + i*256, rr = f >> 4, c = (f & 15) << 2;
            const float* kvb = g_kv + (size_t)(b*SEQ + j0 + rr)*KVC + kvh*HD;
            float4 kk = *(const float4*)(kvb + c);
            uint32_t h0,l0,h1,l1;
            split2(kk.x, kk.y, h0, l0); split2(kk.z, kk.w, h1, l1);
            *(uint2*)&Khi[rr*36 + (c>>1)] = make_uint2(h0, h1);
            *(uint2*)&Klo[rr*36 + (c>>1)] = make_uint2(l0, l1);
        }
        // V loader: transpose-pair -> Vp[jpair][d], stride 72
        {
            int jp = tid >> 4;                  // 0..15
            int dq = (tid & 15) << 2;           // 0..60
            const float* v0p = g_kv + (size_t)(b*SEQ + j0 + 2*jp)*KVC + kvh*HD + 256 + dq;
            const float* v1p = v0p + KVC;
            float4 v0 = *(const float4*)v0p;
            float4 v1 = *(const float4*)v1p;
            uint32_t h0,l0,h1,l1,h2,l2,h3,l3;
            split2(v0.x, v1.x, h0, l0); split2(v0.y, v1.y, h1, l1);
            split2(v0.z, v1.z, h2, l2); split2(v0.w, v1.w, h3, l3);
            *(uint4*)&Vph[jp*72 + dq] = make_uint4(h0, h1, h2, h3);
            *(uint4*)&Vpl[jp*72 + dq] = make_uint4(l0, l1, l2, l3);
        }
        __syncthreads();

        // S = Q K^T : warp tile 16 x 16, 3-term bf16
        float sacc[2][4] = {};
        #pragma unroll
        for (int ks = 0; ks < 4; ks++) {
            const int kb = ks * 8;
            #pragma unroll
            for (int nt = 0; nt < 2; nt++) {
                int rj = (wn*16 + nt*8 + g)*36 + kb + tg;
                uint32_t kh[2] = { Khi[rj], Khi[rj+4] };
                uint32_t kl[2] = { Klo[rj], Klo[rj+4] };
                mma16(sacc[nt], qhi[ks], kh);
                mma16(sacc[nt], qhi[ks], kl);
                mma16(sacc[nt], qlo[ks], kh);
            }
        }
        #pragma unroll
        for (int nt = 0; nt < 2; nt++) {
            int col = wn*16 + nt*8 + 2*tg;
            *(float2*)&Ss[(wm*16 + g)*36 + col]     = make_float2(sacc[nt][0], sacc[nt][1]);
            *(float2*)&Ss[(wm*16 + g + 8)*36 + col] = make_float2(sacc[nt][2], sacc[nt][3]);
        }
        __syncthreads();

        // Online softmax: fp32 stats, emit split P pairs
        {
            const float* prow = &Ss[r*36 + jq*8];
            float p[8];
            float mx = -INFINITY;
            #pragma unroll
            for (int j = 0; j < 8; j++) { p[j] = prow[j]; mx = fmaxf(mx, p[j]); }
            mx = fmaxf(mx, __shfl_xor_sync(0xffffffffu, mx, 1));
            mx = fmaxf(mx, __shfl_xor_sync(0xffffffffu, mx, 2));
            float mold = m_s[r];
            float mnew = fmaxf(mold, mx);
            float lsum = 0.f;
            #pragma unroll
            for (int j = 0; j < 8; j++) { p[j] = __expf(p[j] - mnew); lsum += p[j]; }
            lsum += __shfl_xor_sync(0xffffffffu, lsum, 1);
            lsum += __shfl_xor_sync(0xffffffffu, lsum, 2);
            uint32_t ph[4], pl[4];
            #pragma unroll
            for (int jj = 0; jj < 4; jj++) split2(p[2*jj], p[2*jj+1], ph[jj], pl[jj]);
            *(uint4*)&Psh[r*20 + jq*4] = make_uint4(ph[0], ph[1], ph[2], ph[3]);
            *(uint4*)&Psl[r*20 + jq*4] = make_uint4(pl[0], pl[1], pl[2], pl[3]);
            if (jq == 0) {
                float alpha = __expf(mold - mnew);
                l_s[r] = l_s[r] * alpha + lsum;
                m_s[r] = mnew;
                a_s[r] = alpha;
            }
        }
        __syncthreads();

        // O = O*alpha + P V : warp tile 16 x 32, 3-term bf16
        {
            float al0 = a_s[wm*16 + g];
            float al1 = a_s[wm*16 + g + 8];
            #pragma unroll
            for (int nt = 0; nt < 4; nt++) {
                oacc[nt][0] *= al0; oacc[nt][1] *= al0;
                oacc[nt][2] *= al1; oacc[nt][3] *= al1;
            }
            #pragma unroll
            for (int ks = 0; ks < 2; ks++) {        // 32 j = 2 k16 steps
                const int kb = ks * 8;
                int p0 = (wm*16 + g)*20 + kb + tg;
                int p1 = p0 + 8*20;
                uint32_t ah[4] = { Psh[p0], Psh[p1], Psh[p0+4], Psh[p1+4] };
                uint32_t al[4] = { Psl[p0], Psl[p1], Psl[p0+4], Psl[p1+4] };
                #pragma unroll
                for (int nt = 0; nt < 4; nt++) {
                    int d = wn*32 + nt*8 + g;
                    uint32_t bh[2] = { Vph[(kb+tg)*72 + d], Vph[(kb+tg+4)*72 + d] };
                    uint32_t bl[2] = { Vpl[(kb+tg)*72 + d], Vpl[(kb+tg+4)*72 + d] };
                    mma16(oacc[nt], ah, bh);
                    mma16(oacc[nt], ah, bl);
                    mma16(oacc[nt], al, bh);
                }
            }
        }
        __syncthreads();
    }

    // Normalize + store
    {
        float li0 = 1.f / l_s[wm*16 + g];
        float li1 = 1.f / l_s[wm*16 + g + 8];
        float* o0 = g_ao + (size_t)(b*SEQ + q0 + wm*16 + g)*DIMC + h*HD;
        float* o1 = g_ao + (size_t)(b*SEQ + q0 + wm*16 + g + 8)*DIMC + h*HD;
        #pragma unroll
        for (int nt = 0; nt < 4; nt++) {
            int col = wn*32 + nt*8 + 2*tg;
            *(float2*)(o0 + col) = make_float2(oacc[nt][0]*li0, oacc[nt][1]*li0);
            *(float2*)(o1 + col) = make_float2(oacc[nt][2]*li1, oacc[nt][3]*li1);
        }
    }
}

// ---------------------------------------------------------------------------
extern "C" void kernel_launch(void* const* d_in, const int* in_sizes, int n_in,
                              void* d_out, int out_size)
{
    const float* x     = (const float*)d_in[0];
    const float* Wq    = (const float*)d_in[1];
    const float* Wkv   = (const float*)d_in[2];
    const float* Wproj = (const float*)d_in[3];
    const float* bproj = (const float*)d_in[4];
    float* out = (float*)d_out;

    qkv_gemm<<<dim3(QKVN/128, ROWS/128), 256>>>(x, Wq, Wkv);
    attn_kernel<<<dim3(SEQ/64, NH, BATCH), 256>>>();
    proj_gemm<<<dim3(DIMC/128, ROWS/128), 256>>>(Wproj, bproj, out);
}

// round 7
// speedup vs baseline: 2.5627x; 1.0404x over previous
#include <cuda_runtime.h>
#include <cuda_bf16.h>
#include <math.h>
#include <stdint.h>

#define DIMC   1024
#define NH     16
#define NKV    4
#define HD     64
#define SEQ    2048
#define BATCH  2
#define ROWS   (BATCH*SEQ)      /* 4096 */
#define QKVN   1536
#define SCALE  0.125f

// ---------------- global scratch (allocation-free rule) ----------------
__device__ uint32_t g_xh [ROWS*512],  g_xl [ROWS*512];    // packed A (x, later ao)
__device__ uint32_t g_w1h[QKVN*512],  g_w1l[QKVN*512];    // [Wq*SCALE ; Wkv]
__device__ uint32_t g_w2h[DIMC*512],  g_w2l[DIMC*512];    // Wproj
__device__ uint32_t g_qh [ROWS*512],  g_ql [ROWS*512];    // Q split packed [tok][512]
__device__ uint32_t g_kh [ROWS*128],  g_kl [ROWS*128];    // K split packed [tok][kvh*32+dp]
__device__ float    g_v  [ROWS*256];                       // V fp32 [tok][kvh*64+d]
__device__ float    g_ao [ROWS*DIMC];                      // attention out fp32

// ---------------- helpers ----------------
__device__ __forceinline__ void split2(float x, float y, uint32_t& hi, uint32_t& lo) {
    __nv_bfloat162 h = __floats2bfloat162_rn(x, y);
    float hx = __bfloat162float(__low2bfloat16(h));
    float hy = __bfloat162float(__high2bfloat16(h));
    __nv_bfloat162 l = __floats2bfloat162_rn(x - hx, y - hy);
    hi = *(uint32_t*)&h;
    lo = *(uint32_t*)&l;
}
__device__ __forceinline__ void mma16(float* c, const uint32_t* a, const uint32_t* b) {
    asm volatile(
        "mma.sync.aligned.m16n8k16.row.col.f32.bf16.bf16.f32 "
        "{%0,%1,%2,%3}, {%4,%5,%6,%7}, {%8,%9}, {%0,%1,%2,%3};"
        : "+f"(c[0]), "+f"(c[1]), "+f"(c[2]), "+f"(c[3])
        : "r"(a[0]), "r"(a[1]), "r"(a[2]), "r"(a[3]), "r"(b[0]), "r"(b[1]));
}
__device__ __forceinline__ void cp16(uint32_t* dst, const uint32_t* src) {
    uint32_t s = (uint32_t)__cvta_generic_to_shared(dst);
    asm volatile("cp.async.cg.shared.global [%0], [%1], 16;" :: "r"(s), "l"(src));
}
#define CP_COMMIT asm volatile("cp.async.commit_group;")
#define CP_WAIT1  asm volatile("cp.async.wait_group 1;")
#define CP_WAIT0  asm volatile("cp.async.wait_group 0;")

// ---------------- prep: fp32 -> packed bf16x2 hi/lo ----------------
__global__ void __launch_bounds__(256) prep_pack(
    const float* __restrict__ src, uint32_t* __restrict__ dh,
    uint32_t* __restrict__ dl, int npairs, float scale)
{
    int i = blockIdx.x * 256 + threadIdx.x;
    if (i < npairs) {
        float2 v = *(const float2*)(src + 2*(size_t)i);
        uint32_t h, l;
        split2(v.x * scale, v.y * scale, h, l);
        dh[i] = h; dl[i] = l;
    }
}

// ---------------- GEMM core: cp.async 2-stage, k-tile 32 ----------------
// smem stage layout (u32): Ah[0) Al[2560) Bh[5120) Bl[7680), stage stride 10240
#define GEMM_SMEM (2*10240*4)   /* 81920 B */

__device__ __forceinline__ void gemm_compute(
    const uint32_t* base, int wm, int wn, int g, int tg, float acc[4][4][4])
{
    const uint32_t* Ahi = base;
    const uint32_t* Alo = base + 2560;
    const uint32_t* Bhi = base + 5120;
    const uint32_t* Blo = base + 7680;
    #pragma unroll
    for (int ks = 0; ks < 2; ks++) {
        const int kb = ks * 8;
        uint32_t ah[4][4], al[4][4];
        #pragma unroll
        for (int mt = 0; mt < 4; mt++) {
            int r0 = (wm*64 + mt*16 + g)*20 + kb + tg;
            int r1 = r0 + 160;
            ah[mt][0] = Ahi[r0];   ah[mt][1] = Ahi[r1];
            ah[mt][2] = Ahi[r0+4]; ah[mt][3] = Ahi[r1+4];
            al[mt][0] = Alo[r0];   al[mt][1] = Alo[r1];
            al[mt][2] = Alo[r0+4]; al[mt][3] = Alo[r1+4];
        }
        uint32_t bh[4][2], bl[4][2];
        #pragma unroll
        for (int nt = 0; nt < 4; nt++) {
            int r0 = (wn*32 + nt*8 + g)*20 + kb + tg;
            bh[nt][0] = Bhi[r0]; bh[nt][1] = Bhi[r0+4];
            bl[nt][0] = Blo[r0]; bl[nt][1] = Blo[r0+4];
        }
        #pragma unroll
        for (int mt = 0; mt < 4; mt++)
            #pragma unroll
            for (int nt = 0; nt < 4; nt++) {
                mma16(acc[mt][nt], ah[mt], bh[nt]);
                mma16(acc[mt][nt], ah[mt], bl[nt]);
                mma16(acc[mt][nt], al[mt], bh[nt]);
            }
    }
}

__device__ __forceinline__ void gemm_core(
    const uint32_t* __restrict__ Agh, const uint32_t* __restrict__ Agl,
    const uint32_t* __restrict__ Bgh, const uint32_t* __restrict__ Bgl,
    int m0, int nb, float acc[4][4][4], uint32_t* sm)
{
    const int tid  = threadIdx.x;
    const int lane = tid & 31, warp = tid >> 5;
    const int wm = warp >> 2, wn = warp & 3;
    const int g  = lane >> 2, tg = lane & 3;

    // prologue: stage 0
    {
        #pragma unroll
        for (int i = 0; i < 2; i++) {
            int f = tid + i*256, r = f >> 2, c = (f & 3) << 2;
            cp16(sm + r*20 + c,        Agh + (size_t)(m0 + r)*512 + c);
            cp16(sm + 2560 + r*20 + c, Agl + (size_t)(m0 + r)*512 + c);
            cp16(sm + 5120 + r*20 + c, Bgh + (size_t)(nb + r)*512 + c);
            cp16(sm + 7680 + r*20 + c, Bgl + (size_t)(nb + r)*512 + c);
        }
        CP_COMMIT;
    }
    for (int kt = 0; kt < 32; kt++) {
        const int st = kt & 1;
        if (kt < 31) {
            const int pc = (kt + 1) * 16;
            uint32_t* nxt = sm + (st ^ 1) * 10240;
            #pragma unroll
            for (int i = 0; i < 2; i++) {
                int f = tid + i*256, r = f >> 2, c = (f & 3) << 2;
                cp16(nxt + r*20 + c,        Agh + (size_t)(m0 + r)*512 + pc + c);
                cp16(nxt + 2560 + r*20 + c, Agl + (size_t)(m0 + r)*512 + pc + c);
                cp16(nxt + 5120 + r*20 + c, Bgh + (size_t)(nb + r)*512 + pc + c);
                cp16(nxt + 7680 + r*20 + c, Bgl + (size_t)(nb + r)*512 + pc + c);
            }
        }
        CP_COMMIT;
        if (kt < 31) { CP_WAIT1; } else { CP_WAIT0; }
        __syncthreads();
        gemm_compute(sm + st*10240, wm, wn, g, tg, acc);
        __syncthreads();
    }
}

// qkv: A = packed x, B = packed [Wq*SCALE; Wkv]. Epilogue routes by column:
//   [0,1024) -> Q split-packed, [1024,1280) -> K split-packed, [1280,1536) -> V fp32
__global__ void __launch_bounds__(256) qkv_gemm()
{
    extern __shared__ uint32_t smq[];
    const int m0 = blockIdx.y * 128;
    const int nb = blockIdx.x * 128;
    const int lane = threadIdx.x & 31, warp = threadIdx.x >> 5;
    const int wm = warp >> 2, wn = warp & 3;
    const int g = lane >> 2, tg = lane & 3;

    float acc[4][4][4] = {};
    gemm_core(g_xh, g_xl, g_w1h, g_w1l, m0, nb, acc, smq);

    #pragma unroll
    for (int mt = 0; mt < 4; mt++) {
        int row = m0 + wm*64 + mt*16 + g;
        #pragma unroll
        for (int nt = 0; nt < 4; nt++) {
            int col = nb + wn*32 + nt*8 + 2*tg;
            if (nb < 1024) {
                int pc = col >> 1;
                uint32_t h, l;
                split2(acc[mt][nt][0], acc[mt][nt][1], h, l);
                g_qh[(size_t)row*512 + pc] = h; g_ql[(size_t)row*512 + pc] = l;
                split2(acc[mt][nt][2], acc[mt][nt][3], h, l);
                g_qh[(size_t)(row+8)*512 + pc] = h; g_ql[(size_t)(row+8)*512 + pc] = l;
            } else if (nb < 1280) {
                int pc = (col - 1024) >> 1;
                uint32_t h, l;
                split2(acc[mt][nt][0], acc[mt][nt][1], h, l);
                g_kh[(size_t)row*128 + pc] = h; g_kl[(size_t)row*128 + pc] = l;
                split2(acc[mt][nt][2], acc[mt][nt][3], h, l);
                g_kh[(size_t)(row+8)*128 + pc] = h; g_kl[(size_t)(row+8)*128 + pc] = l;
            } else {
                int cv = col - 1280;
                *(float2*)(g_v + (size_t)row*256 + cv) =
                    make_float2(acc[mt][nt][0], acc[mt][nt][1]);
                *(float2*)(g_v + (size_t)(row+8)*256 + cv) =
                    make_float2(acc[mt][nt][2], acc[mt][nt][3]);
            }
        }
    }
}

__global__ void __launch_bounds__(256) proj_gemm(
    const float* __restrict__ bproj, float* __restrict__ out)
{
    extern __shared__ uint32_t smp[];
    const int m0 = blockIdx.y * 128;
    const int nb = blockIdx.x * 128;
    const int lane = threadIdx.x & 31, warp = threadIdx.x >> 5;
    const int wm = warp >> 2, wn = warp & 3;
    const int g = lane >> 2, tg = lane & 3;

    float acc[4][4][4] = {};
    gemm_core(g_xh, g_xl, g_w2h, g_w2l, m0, nb, acc, smp);

    #pragma unroll
    for (int mt = 0; mt < 4; mt++) {
        int r0 = m0 + wm*64 + mt*16 + g;
        #pragma unroll
        for (int nt = 0; nt < 4; nt++) {
            int col = nb + wn*32 + nt*8 + 2*tg;
            float b0 = bproj[col], b1 = bproj[col+1];
            *(float2*)(out + (size_t)r0*DIMC + col) =
                make_float2(acc[mt][nt][0] + b0, acc[mt][nt][1] + b1);
            *(float2*)(out + (size_t)(r0+8)*DIMC + col) =
                make_float2(acc[mt][nt][2] + b0, acc[mt][nt][3] + b1);
        }
    }
}

// ---------------- attention: pre-split Q/K, j-tile 32 ----------------
__global__ void __launch_bounds__(256) attn_kernel()
{
    __shared__ uint32_t pool[9472];
    __shared__ float m_s[64], l_s[64], a_s[64];
    uint32_t* Qh  = pool;               // 64*36 (phase 0 only)
    uint32_t* Ql  = pool + 2304;
    uint32_t* Khi = pool;               // 32*36
    uint32_t* Klo = pool + 1152;
    uint32_t* Vph = pool + 2304;        // 16*72
    uint32_t* Vpl = pool + 3456;
    float*    Ss  = (float*)(pool + 4608);  // 64*36
    uint32_t* Psh = pool + 6912;        // 64*20
    uint32_t* Psl = pool + 8192;

    const int tid  = threadIdx.x;
    const int lane = tid & 31;
    const int warp = tid >> 5;
    const int wm   = warp >> 1;
    const int wn   = warp & 1;
    const int g    = lane >> 2;
    const int tg   = lane & 3;

    const int q0  = blockIdx.x * 64;
    const int h   = blockIdx.y;
    const int b   = blockIdx.z;
    const int kvh = h >> 2;

    const int r  = tid >> 2;
    const int jq = tid & 3;

    // Phase 0: stage pre-split Q (already scaled) -> registers
    #pragma unroll
    for (int i = 0; i < 2; i++) {
        int f = tid + i*256, rr = f >> 3, c = (f & 7) << 2;
        const size_t src = (size_t)(b*SEQ + q0 + rr)*512 + h*32 + c;
        *(uint4*)&Qh[rr*36 + c] = *(const uint4*)&g_qh[src];
        *(uint4*)&Ql[rr*36 + c] = *(const uint4*)&g_ql[src];
    }
    if (tid < 64) { m_s[tid] = -INFINITY; l_s[tid] = 0.f; }
    __syncthreads();

    uint32_t qhi[4][4], qlo[4][4];
    #pragma unroll
    for (int ks = 0; ks < 4; ks++) {
        int r0 = (wm*16 + g)*36 + ks*8 + tg;
        int r1 = r0 + 8*36;
        qhi[ks][0] = Qh[r0];   qhi[ks][1] = Qh[r1];
        qhi[ks][2] = Qh[r0+4]; qhi[ks][3] = Qh[r1+4];
        qlo[ks][0] = Ql[r0];   qlo[ks][1] = Ql[r1];
        qlo[ks][2] = Ql[r0+4]; qlo[ks][3] = Ql[r1+4];
    }
    float oacc[4][4] = {};
    __syncthreads();

    for (int j0 = 0; j0 < SEQ; j0 += 32) {
        // K: raw pre-split copies (32 tok x 32 pairs)
        {
            int f = tid, rr = f >> 3, c = (f & 7) << 2;
            const size_t src = (size_t)(b*SEQ + j0 + rr)*128 + kvh*32 + c;
            *(uint4*)&Khi[rr*36 + c] = *(const uint4*)&g_kh[src];
            *(uint4*)&Klo[rr*36 + c] = *(const uint4*)&g_kl[src];
        }
        // V: fp32 -> token-pair split (16 pairs x 64 d)
        {
            int jp = tid >> 4, dq = (tid & 15) << 2;
            const float* v0p = g_v + (size_t)(b*SEQ + j0 + 2*jp)*256 + kvh*64 + dq;
            float4 v0 = *(const float4*)v0p;
            float4 v1 = *(const float4*)(v0p + 256);
            uint32_t h0,l0,h1,l1,h2,l2,h3,l3;
            split2(v0.x, v1.x, h0, l0); split2(v0.y, v1.y, h1, l1);
            split2(v0.z, v1.z, h2, l2); split2(v0.w, v1.w, h3, l3);
            *(uint4*)&Vph[jp*72 + dq] = make_uint4(h0, h1, h2, h3);
            *(uint4*)&Vpl[jp*72 + dq] = make_uint4(l0, l1, l2, l3);
        }
        __syncthreads();

        // S = Q K^T
        float sacc[2][4] = {};
        #pragma unroll
        for (int ks = 0; ks < 4; ks++) {
            const int kb = ks * 8;
            #pragma unroll
            for (int nt = 0; nt < 2; nt++) {
                int rj = (wn*16 + nt*8 + g)*36 + kb + tg;
                uint32_t kh[2] = { Khi[rj], Khi[rj+4] };
                uint32_t kl[2] = { Klo[rj], Klo[rj+4] };
                mma16(sacc[nt], qhi[ks], kh);
                mma16(sacc[nt], qhi[ks], kl);
                mma16(sacc[nt], qlo[ks], kh);
            }
        }
        #pragma unroll
        for (int nt = 0; nt < 2; nt++) {
            int col = wn*16 + nt*8 + 2*tg;
            *(float2*)&Ss[(wm*16 + g)*36 + col]     = make_float2(sacc[nt][0], sacc[nt][1]);
            *(float2*)&Ss[(wm*16 + g + 8)*36 + col] = make_float2(sacc[nt][2], sacc[nt][3]);
        }
        __syncthreads();

        // online softmax -> split P
        {
            const float* prow = &Ss[r*36 + jq*8];
            float p[8];
            float mx = -INFINITY;
            #pragma unroll
            for (int j = 0; j < 8; j++) { p[j] = prow[j]; mx = fmaxf(mx, p[j]); }
            mx = fmaxf(mx, __shfl_xor_sync(0xffffffffu, mx, 1));
            mx = fmaxf(mx, __shfl_xor_sync(0xffffffffu, mx, 2));
            float mold = m_s[r];
            float mnew = fmaxf(mold, mx);
            float lsum = 0.f;
            #pragma unroll
            for (int j = 0; j < 8; j++) { p[j] = __expf(p[j] - mnew); lsum += p[j]; }
            lsum += __shfl_xor_sync(0xffffffffu, lsum, 1);
            lsum += __shfl_xor_sync(0xffffffffu, lsum, 2);
            uint32_t ph[4], pl[4];
            #pragma unroll
            for (int jj = 0; jj < 4; jj++) split2(p[2*jj], p[2*jj+1], ph[jj], pl[jj]);
            *(uint4*)&Psh[r*20 + jq*4] = make_uint4(ph[0], ph[1], ph[2], ph[3]);
            *(uint4*)&Psl[r*20 + jq*4] = make_uint4(pl[0], pl[1], pl[2], pl[3]);
            if (jq == 0) {
                float alpha = __expf(mold - mnew);
                l_s[r] = l_s[r] * alpha + lsum;
                m_s[r] = mnew;
                a_s[r] = alpha;
            }
        }
        __syncthreads();

        // O = O*alpha + P V
        {
            float al0 = a_s[wm*16 + g];
            float al1 = a_s[wm*16 + g + 8];
            #pragma unroll
            for (int nt = 0; nt < 4; nt++) {
                oacc[nt][0] *= al0; oacc[nt][1] *= al0;
                oacc[nt][2] *= al1; oacc[nt][3] *= al1;
            }
            #pragma unroll
            for (int ks = 0; ks < 2; ks++) {
                const int kb = ks * 8;
                int p0 = (wm*16 + g)*20 + kb + tg;
                int p1 = p0 + 160;
                uint32_t ah[4] = { Psh[p0], Psh[p1], Psh[p0+4], Psh[p1+4] };
                uint32_t al[4] = { Psl[p0], Psl[p1], Psl[p0+4], Psl[p1+4] };
                #pragma unroll
                for (int nt = 0; nt < 4; nt++) {
                    int d = wn*32 + nt*8 + g;
                    uint32_t bh[2] = { Vph[(kb+tg)*72 + d], Vph[(kb+tg+4)*72 + d] };
                    uint32_t bl[2] = { Vpl[(kb+tg)*72 + d], Vpl[(kb+tg+4)*72 + d] };
                    mma16(oacc[nt], ah, bh);
                    mma16(oacc[nt], ah, bl);
                    mma16(oacc[nt], al, bh);
                }
            }
        }
        __syncthreads();
    }

    // normalize + store fp32 ao
    {
        float li0 = 1.f / l_s[wm*16 + g];
        float li1 = 1.f / l_s[wm*16 + g + 8];
        float* o0 = g_ao + (size_t)(b*SEQ + q0 + wm*16 + g)*DIMC + h*HD;
        float* o1 = g_ao + (size_t)(b*SEQ + q0 + wm*16 + g + 8)*DIMC + h*HD;
        #pragma unroll
        for (int nt = 0; nt < 4; nt++) {
            int col = wn*32 + nt*8 + 2*tg;
            *(float2*)(o0 + col) = make_float2(oacc[nt][0]*li0, oacc[nt][1]*li0);
            *(float2*)(o1 + col) = make_float2(oacc[nt][2]*li1, oacc[nt][3]*li1);
        }
    }
}

// ---------------- host ----------------
extern "C" void kernel_launch(void* const* d_in, const int* in_sizes, int n_in,
                              void* d_out, int out_size)
{
    const float* x     = (const float*)d_in[0];
    const float* Wq    = (const float*)d_in[1];
    const float* Wkv   = (const float*)d_in[2];
    const float* Wproj = (const float*)d_in[3];
    const float* bproj = (const float*)d_in[4];
    float* out = (float*)d_out;

    static int smem_ok = 0;
    if (!smem_ok) {
        (void)cudaFuncSetAttribute(qkv_gemm,
            cudaFuncAttributeMaxDynamicSharedMemorySize, GEMM_SMEM);
        (void)cudaFuncSetAttribute(proj_gemm,
            cudaFuncAttributeMaxDynamicSharedMemorySize, GEMM_SMEM);
        smem_ok = 1;
    }

    uint32_t *xh, *xl, *w1h, *w1l, *w2h, *w2l;
    (void)cudaGetSymbolAddress((void**)&xh,  g_xh);
    (void)cudaGetSymbolAddress((void**)&xl,  g_xl);
    (void)cudaGetSymbolAddress((void**)&w1h, g_w1h);
    (void)cudaGetSymbolAddress((void**)&w1l, g_w1l);
    (void)cudaGetSymbolAddress((void**)&w2h, g_w2h);
    (void)cudaGetSymbolAddress((void**)&w2l, g_w2l);
    float* ao;
    (void)cudaGetSymbolAddress((void**)&ao, g_ao);

    // pack inputs
    prep_pack<<<(1024*512+255)/256, 256>>>(Wq,  w1h, w1l, 1024*512, SCALE);
    prep_pack<<<(512*512+255)/256,  256>>>(Wkv, w1h + 1024*512, w1l + 1024*512, 512*512, 1.f);
    prep_pack<<<(1024*512+255)/256, 256>>>(Wproj, w2h, w2l, 1024*512, 1.f);
    prep_pack<<<(ROWS*512+255)/256, 256>>>(x, xh, xl, ROWS*512, 1.f);

    qkv_gemm<<<dim3(QKVN/128, ROWS/128), 256, GEMM_SMEM>>>();
    attn_kernel<<<dim3(SEQ/64, NH, BATCH), 256>>>();

    // repack attention output as GEMM A (reuses x buffers)
    prep_pack<<<(ROWS*512+255)/256, 256>>>(ao, xh, xl, ROWS*512, 1.f);
    proj_gemm<<<dim3(DIMC/128, ROWS/128), 256, GEMM_SMEM>>>(bproj, out);
}

// round 8
// speedup vs baseline: 2.7968x; 1.0913x over previous
#include <cuda_runtime.h>
#include <cuda_bf16.h>
#include <math.h>
#include <stdint.h>

#define DIMC   1024
#define NH     16
#define NKV    4
#define HD     64
#define SEQ    2048
#define BATCH  2
#define ROWS   (BATCH*SEQ)      /* 4096 */
#define QKVN   1536
#define SCALE  0.125f

// ---------------- global scratch (allocation-free rule) ----------------
__device__ uint32_t g_xh [ROWS*512],  g_xl [ROWS*512];    // packed A (x, later ao)
__device__ uint32_t g_w1h[QKVN*512],  g_w1l[QKVN*512];    // [Wq*SCALE ; Wkv]
__device__ uint32_t g_w2h[DIMC*512],  g_w2l[DIMC*512];    // Wproj
__device__ uint32_t g_qh [ROWS*512],  g_ql [ROWS*512];    // Q split packed [tok][512]
__device__ uint32_t g_kh [ROWS*128],  g_kl [ROWS*128];    // K split packed [tok][kvh*32+dp]
__device__ float    g_v  [ROWS*256];                       // V fp32 [tok][kvh*64+d]
__device__ uint32_t g_vh [BATCH*NKV*1024*64], g_vl[BATCH*NKV*1024*64]; // V split pair-transposed
__device__ float    g_ao [ROWS*DIMC];                      // attention out fp32

// ---------------- helpers ----------------
__device__ __forceinline__ void split2(float x, float y, uint32_t& hi, uint32_t& lo) {
    __nv_bfloat162 h = __floats2bfloat162_rn(x, y);
    float hx = __bfloat162float(__low2bfloat16(h));
    float hy = __bfloat162float(__high2bfloat16(h));
    __nv_bfloat162 l = __floats2bfloat162_rn(x - hx, y - hy);
    hi = *(uint32_t*)&h;
    lo = *(uint32_t*)&l;
}
__device__ __forceinline__ void mma16(float* c, const uint32_t* a, const uint32_t* b) {
    asm volatile(
        "mma.sync.aligned.m16n8k16.row.col.f32.bf16.bf16.f32 "
        "{%0,%1,%2,%3}, {%4,%5,%6,%7}, {%8,%9}, {%0,%1,%2,%3};"
        : "+f"(c[0]), "+f"(c[1]), "+f"(c[2]), "+f"(c[3])
        : "r"(a[0]), "r"(a[1]), "r"(a[2]), "r"(a[3]), "r"(b[0]), "r"(b[1]));
}
__device__ __forceinline__ void cp16(uint32_t* dst, const uint32_t* src) {
    uint32_t s = (uint32_t)__cvta_generic_to_shared(dst);
    asm volatile("cp.async.cg.shared.global [%0], [%1], 16;" :: "r"(s), "l"(src));
}
#define CP_COMMIT asm volatile("cp.async.commit_group;")
#define CP_WAIT1  asm volatile("cp.async.wait_group 1;")
#define CP_WAIT0  asm volatile("cp.async.wait_group 0;")

// ---------------- prep kernels ----------------
__global__ void __launch_bounds__(256) prep_pack(
    const float* __restrict__ src, uint32_t* __restrict__ dh,
    uint32_t* __restrict__ dl, int npairs, float scale)
{
    int i = blockIdx.x * 256 + threadIdx.x;
    if (i < npairs) {
        float2 v = *(const float2*)(src + 2*(size_t)i);
        uint32_t h, l;
        split2(v.x * scale, v.y * scale, h, l);
        dh[i] = h; dl[i] = l;
    }
}

// V fp32 [tok][kvh*64+d] -> split packed pair-transposed [b][kvh][jp][d]
__global__ void __launch_bounds__(256) prep_v()
{
    int i = blockIdx.x * 256 + threadIdx.x;     // 131072 total
    int dq  = (i & 15) << 2;
    int kvh = (i >> 4) & 3;
    int gp  = i >> 6;                           // global pair 0..2047
    int b   = gp >> 10, jp = gp & 1023;
    const float* v0p = g_v + (size_t)(b*SEQ + 2*jp)*256 + kvh*64 + dq;
    float4 v0 = *(const float4*)v0p;
    float4 v1 = *(const float4*)(v0p + 256);
    uint32_t h0,l0,h1,l1,h2,l2,h3,l3;
    split2(v0.x, v1.x, h0, l0); split2(v0.y, v1.y, h1, l1);
    split2(v0.z, v1.z, h2, l2); split2(v0.w, v1.w, h3, l3);
    size_t dst = ((size_t)(b*NKV + kvh)*1024 + jp)*64 + dq;
    *(uint4*)&g_vh[dst] = make_uint4(h0, h1, h2, h3);
    *(uint4*)&g_vl[dst] = make_uint4(l0, l1, l2, l3);
}

// ---------------- GEMM core: cp.async 2-stage, k-tile 32 ----------------
#define GEMM_SMEM (2*10240*4)   /* 81920 B */

__device__ __forceinline__ void gemm_compute(
    const uint32_t* base, int wm, int wn, int g, int tg, float acc[4][4][4])
{
    const uint32_t* Ahi = base;
    const uint32_t* Alo = base + 2560;
    const uint32_t* Bhi = base + 5120;
    const uint32_t* Blo = base + 7680;
    #pragma unroll
    for (int ks = 0; ks < 2; ks++) {
        const int kb = ks * 8;
        uint32_t ah[4][4], al[4][4];
        #pragma unroll
        for (int mt = 0; mt < 4; mt++) {
            int r0 = (wm*64 + mt*16 + g)*20 + kb + tg;
            int r1 = r0 + 160;
            ah[mt][0] = Ahi[r0];   ah[mt][1] = Ahi[r1];
            ah[mt][2] = Ahi[r0+4]; ah[mt][3] = Ahi[r1+4];
            al[mt][0] = Alo[r0];   al[mt][1] = Alo[r1];
            al[mt][2] = Alo[r0+4]; al[mt][3] = Alo[r1+4];
        }
        uint32_t bh[4][2], bl[4][2];
        #pragma unroll
        for (int nt = 0; nt < 4; nt++) {
            int r0 = (wn*32 + nt*8 + g)*20 + kb + tg;
            bh[nt][0] = Bhi[r0]; bh[nt][1] = Bhi[r0+4];
            bl[nt][0] = Blo[r0]; bl[nt][1] = Blo[r0+4];
        }
        #pragma unroll
        for (int mt = 0; mt < 4; mt++)
            #pragma unroll
            for (int nt = 0; nt < 4; nt++) {
                mma16(acc[mt][nt], ah[mt], bh[nt]);
                mma16(acc[mt][nt], ah[mt], bl[nt]);
                mma16(acc[mt][nt], al[mt], bh[nt]);
            }
    }
}

__device__ __forceinline__ void gemm_core(
    const uint32_t* __restrict__ Agh, const uint32_t* __restrict__ Agl,
    const uint32_t* __restrict__ Bgh, const uint32_t* __restrict__ Bgl,
    int m0, int nb, float acc[4][4][4], uint32_t* sm)
{
    const int tid  = threadIdx.x;
    const int lane = tid & 31, warp = tid >> 5;
    const int wm = warp >> 2, wn = warp & 3;
    const int g  = lane >> 2, tg = lane & 3;

    {
        #pragma unroll
        for (int i = 0; i < 2; i++) {
            int f = tid + i*256, r = f >> 2, c = (f & 3) << 2;
            cp16(sm + r*20 + c,        Agh + (size_t)(m0 + r)*512 + c);
            cp16(sm + 2560 + r*20 + c, Agl + (size_t)(m0 + r)*512 + c);
            cp16(sm + 5120 + r*20 + c, Bgh + (size_t)(nb + r)*512 + c);
            cp16(sm + 7680 + r*20 + c, Bgl + (size_t)(nb + r)*512 + c);
        }
        CP_COMMIT;
    }
    for (int kt = 0; kt < 32; kt++) {
        const int st = kt & 1;
        if (kt < 31) {
            const int pc = (kt + 1) * 16;
            uint32_t* nxt = sm + (st ^ 1) * 10240;
            #pragma unroll
            for (int i = 0; i < 2; i++) {
                int f = tid + i*256, r = f >> 2, c = (f & 3) << 2;
                cp16(nxt + r*20 + c,        Agh + (size_t)(m0 + r)*512 + pc + c);
                cp16(nxt + 2560 + r*20 + c, Agl + (size_t)(m0 + r)*512 + pc + c);
                cp16(nxt + 5120 + r*20 + c, Bgh + (size_t)(nb + r)*512 + pc + c);
                cp16(nxt + 7680 + r*20 + c, Bgl + (size_t)(nb + r)*512 + pc + c);
            }
        }
        CP_COMMIT;
        if (kt < 31) { CP_WAIT1; } else { CP_WAIT0; }
        __syncthreads();
        gemm_compute(sm + st*10240, wm, wn, g, tg, acc);
        __syncthreads();
    }
}

// qkv epilogue routes: [0,1024)->Q packed, [1024,1280)->K packed, [1280,1536)->V fp32
__global__ void __launch_bounds__(256) qkv_gemm()
{
    extern __shared__ uint32_t smq[];
    const int m0 = blockIdx.y * 128;
    const int nb = blockIdx.x * 128;
    const int lane = threadIdx.x & 31, warp = threadIdx.x >> 5;
    const int wm = warp >> 2, wn = warp & 3;
    const int g = lane >> 2, tg = lane & 3;

    float acc[4][4][4] = {};
    gemm_core(g_xh, g_xl, g_w1h, g_w1l, m0, nb, acc, smq);

    #pragma unroll
    for (int mt = 0; mt < 4; mt++) {
        int row = m0 + wm*64 + mt*16 + g;
        #pragma unroll
        for (int nt = 0; nt < 4; nt++) {
            int col = nb + wn*32 + nt*8 + 2*tg;
            if (nb < 1024) {
                int pc = col >> 1;
                uint32_t h, l;
                split2(acc[mt][nt][0], acc[mt][nt][1], h, l);
                g_qh[(size_t)row*512 + pc] = h; g_ql[(size_t)row*512 + pc] = l;
                split2(acc[mt][nt][2], acc[mt][nt][3], h, l);
                g_qh[(size_t)(row+8)*512 + pc] = h; g_ql[(size_t)(row+8)*512 + pc] = l;
            } else if (nb < 1280) {
                int pc = (col - 1024) >> 1;
                uint32_t h, l;
                split2(acc[mt][nt][0], acc[mt][nt][1], h, l);
                g_kh[(size_t)row*128 + pc] = h; g_kl[(size_t)row*128 + pc] = l;
                split2(acc[mt][nt][2], acc[mt][nt][3], h, l);
                g_kh[(size_t)(row+8)*128 + pc] = h; g_kl[(size_t)(row+8)*128 + pc] = l;
            } else {
                int cv = col - 1280;
                *(float2*)(g_v + (size_t)row*256 + cv) =
                    make_float2(acc[mt][nt][0], acc[mt][nt][1]);
                *(float2*)(g_v + (size_t)(row+8)*256 + cv) =
                    make_float2(acc[mt][nt][2], acc[mt][nt][3]);
            }
        }
    }
}

__global__ void __launch_bounds__(256) proj_gemm(
    const float* __restrict__ bproj, float* __restrict__ out)
{
    extern __shared__ uint32_t smp[];
    const int m0 = blockIdx.y * 128;
    const int nb = blockIdx.x * 128;
    const int lane = threadIdx.x & 31, warp = threadIdx.x >> 5;
    const int wm = warp >> 2, wn = warp & 3;
    const int g = lane >> 2, tg = lane & 3;

    float acc[4][4][4] = {};
    gemm_core(g_xh, g_xl, g_w2h, g_w2l, m0, nb, acc, smp);

    #pragma unroll
    for (int mt = 0; mt < 4; mt++) {
        int r0 = m0 + wm*64 + mt*16 + g;
        #pragma unroll
        for (int nt = 0; nt < 4; nt++) {
            int col = nb + wn*32 + nt*8 + 2*tg;
            float b0 = bproj[col], b1 = bproj[col+1];
            *(float2*)(out + (size_t)r0*DIMC + col) =
                make_float2(acc[mt][nt][0] + b0, acc[mt][nt][1] + b1);
            *(float2*)(out + (size_t)(r0+8)*DIMC + col) =
                make_float2(acc[mt][nt][2] + b0, acc[mt][nt][3] + b1);
        }
    }
}

// ---------------------------------------------------------------------------
// Attention v2: 128 Q rows/CTA, warp owns 16 rows x ALL j. Register softmax.
// j-tile 32, cp.async double-buffered K/V (stage = Kh|Kl|Vh|Vl = 4608 u32).
// ---------------------------------------------------------------------------
__global__ void __launch_bounds__(256) attn_kernel()
{
    __shared__ uint32_t sm[2*4608];     // 36864 B

    const int tid  = threadIdx.x;
    const int lane = tid & 31;
    const int warp = tid >> 5;
    const int g    = lane >> 2;
    const int tg   = lane & 3;

    const int q0  = blockIdx.x * 128;
    const int h   = blockIdx.y;
    const int b   = blockIdx.z;
    const int kvh = h >> 2;

    // Q fragments (pre-scaled, pre-split): 4 k16-steps
    uint32_t qh[4][4], ql[4][4];
    {
        const size_t r0 = (size_t)(b*SEQ + q0 + warp*16 + g)*512 + h*32;
        const size_t r1 = r0 + 8*512;
        #pragma unroll
        for (int ks = 0; ks < 4; ks++) {
            qh[ks][0] = g_qh[r0 + ks*8 + tg];
            qh[ks][1] = g_qh[r1 + ks*8 + tg];
            qh[ks][2] = g_qh[r0 + ks*8 + tg + 4];
            qh[ks][3] = g_qh[r1 + ks*8 + tg + 4];
            ql[ks][0] = g_ql[r0 + ks*8 + tg];
            ql[ks][1] = g_ql[r1 + ks*8 + tg];
            ql[ks][2] = g_ql[r0 + ks*8 + tg + 4];
            ql[ks][3] = g_ql[r1 + ks*8 + tg + 4];
        }
    }

    float oacc[8][4] = {};
    float m0 = -INFINITY, m1 = -INFINITY, l0 = 0.f, l1 = 0.f;

    const size_t kbase = (size_t)(b*SEQ)*128 + kvh*32;
    const size_t vbase = (size_t)(b*NKV + kvh)*1024*64;

    // stage loader: Kh[j*36+c] Kl VhP[jp*72+d] VlP
    auto load_stage = [&](int st, int j0) {
        uint32_t* dst = sm + st*4608;
        const size_t ks_ = kbase + (size_t)j0*128;
        const size_t vs_ = vbase + (size_t)(j0 >> 1)*64;
        #pragma unroll
        for (int i = 0; i < 4; i++) {
            int idx = tid + i*256;
            int a = idx >> 8, j = idx & 255;
            if (a < 2) {
                int r = j >> 3, c = (j & 7) << 2;
                const uint32_t* s = (a ? g_kl : g_kh) + ks_ + (size_t)r*128 + c;
                cp16(dst + a*1152 + r*36 + c, s);
            } else {
                int r = j >> 4, c = (j & 15) << 2;
                const uint32_t* s = (a == 3 ? g_vl : g_vh) + vs_ + (size_t)r*64 + c;
                cp16(dst + 2304 + (a - 2)*1152 + r*72 + c, s);
            }
        }
        CP_COMMIT;
    };

    load_stage(0, 0);

    for (int it = 0; it < SEQ/32; it++) {
        CP_WAIT0;
        __syncthreads();                    // stage ready + prev compute done
        if (it < SEQ/32 - 1) load_stage((it + 1) & 1, (it + 1)*32);

        const uint32_t* Kh = sm + (it & 1)*4608;
        const uint32_t* Kl = Kh + 1152;
        const uint32_t* Vh = Kh + 2304;
        const uint32_t* Vl = Kh + 3456;

        // S = Q K^T : 4 n8 tiles (j 0..31), 3-term
        float sacc[4][4] = {};
        #pragma unroll
        for (int ks = 0; ks < 4; ks++) {
            #pragma unroll
            for (int nt = 0; nt < 4; nt++) {
                int rj = (nt*8 + g)*36 + ks*8 + tg;
                uint32_t kh2[2] = { Kh[rj], Kh[rj+4] };
                uint32_t kl2[2] = { Kl[rj], Kl[rj+4] };
                mma16(sacc[nt], qh[ks], kh2);
                mma16(sacc[nt], qh[ks], kl2);
                mma16(sacc[nt], ql[ks], kh2);
            }
        }

        // warp-local online softmax (rows g and g+8)
        float mx0 = -INFINITY, mx1 = -INFINITY;
        #pragma unroll
        for (int nt = 0; nt < 4; nt++) {
            mx0 = fmaxf(mx0, fmaxf(sacc[nt][0], sacc[nt][1]));
            mx1 = fmaxf(mx1, fmaxf(sacc[nt][2], sacc[nt][3]));
        }
        mx0 = fmaxf(mx0, __shfl_xor_sync(0xffffffffu, mx0, 1));
        mx0 = fmaxf(mx0, __shfl_xor_sync(0xffffffffu, mx0, 2));
        mx1 = fmaxf(mx1, __shfl_xor_sync(0xffffffffu, mx1, 1));
        mx1 = fmaxf(mx1, __shfl_xor_sync(0xffffffffu, mx1, 2));
        float mn0 = fmaxf(m0, mx0), mn1 = fmaxf(m1, mx1);
        float ls0 = 0.f, ls1 = 0.f;
        #pragma unroll
        for (int nt = 0; nt < 4; nt++) {
            sacc[nt][0] = __expf(sacc[nt][0] - mn0); ls0 += sacc[nt][0];
            sacc[nt][1] = __expf(sacc[nt][1] - mn0); ls0 += sacc[nt][1];
            sacc[nt][2] = __expf(sacc[nt][2] - mn1); ls1 += sacc[nt][2];
            sacc[nt][3] = __expf(sacc[nt][3] - mn1); ls1 += sacc[nt][3];
        }
        ls0 += __shfl_xor_sync(0xffffffffu, ls0, 1);
        ls0 += __shfl_xor_sync(0xffffffffu, ls0, 2);
        ls1 += __shfl_xor_sync(0xffffffffu, ls1, 1);
        ls1 += __shfl_xor_sync(0xffffffffu, ls1, 2);
        float a0 = __expf(m0 - mn0), a1 = __expf(m1 - mn1);
        l0 = l0*a0 + ls0; l1 = l1*a1 + ls1;
        m0 = mn0; m1 = mn1;
        #pragma unroll
        for (int nt = 0; nt < 8; nt++) {
            oacc[nt][0] *= a0; oacc[nt][1] *= a0;
            oacc[nt][2] *= a1; oacc[nt][3] *= a1;
        }

        // P·V : P fragments packed in-place from S fragments (no smem)
        #pragma unroll
        for (int ks = 0; ks < 2; ks++) {
            uint32_t ah[4], al[4];
            split2(sacc[2*ks][0],   sacc[2*ks][1],   ah[0], al[0]);
            split2(sacc[2*ks][2],   sacc[2*ks][3],   ah[1], al[1]);
            split2(sacc[2*ks+1][0], sacc[2*ks+1][1], ah[2], al[2]);
            split2(sacc[2*ks+1][2], sacc[2*ks+1][3], ah[3], al[3]);
            #pragma unroll
            for (int nt = 0; nt < 8; nt++) {
                int d = nt*8 + g;
                uint32_t bh2[2] = { Vh[(ks*8 + tg)*72 + d], Vh[(ks*8 + tg + 4)*72 + d] };
                uint32_t bl2[2] = { Vl[(ks*8 + tg)*72 + d], Vl[(ks*8 + tg + 4)*72 + d] };
                mma16(oacc[nt], ah, bh2);
                mma16(oacc[nt], ah, bl2);
                mma16(oacc[nt], al, bh2);
            }
        }
    }

    // normalize + store
    {
        float li0 = 1.f / l0, li1 = 1.f / l1;
        float* o0 = g_ao + (size_t)(b*SEQ + q0 + warp*16 + g)*DIMC + h*HD;
        float* o1 = o0 + 8*DIMC;
        #pragma unroll
        for (int nt = 0; nt < 8; nt++) {
            int col = nt*8 + 2*tg;
            *(float2*)(o0 + col) = make_float2(oacc[nt][0]*li0, oacc[nt][1]*li0);
            *(float2*)(o1 + col) = make_float2(oacc[nt][2]*li1, oacc[nt][3]*li1);
        }
    }
}

// ---------------- host ----------------
extern "C" void kernel_launch(void* const* d_in, const int* in_sizes, int n_in,
                              void* d_out, int out_size)
{
    const float* x     = (const float*)d_in[0];
    const float* Wq    = (const float*)d_in[1];
    const float* Wkv   = (const float*)d_in[2];
    const float* Wproj = (const float*)d_in[3];
    const float* bproj = (const float*)d_in[4];
    float* out = (float*)d_out;

    (void)cudaFuncSetAttribute(qkv_gemm,
        cudaFuncAttributeMaxDynamicSharedMemorySize, GEMM_SMEM);
    (void)cudaFuncSetAttribute(proj_gemm,
        cudaFuncAttributeMaxDynamicSharedMemorySize, GEMM_SMEM);

    uint32_t *xh, *xl, *w1h, *w1l, *w2h, *w2l;
    (void)cudaGetSymbolAddress((void**)&xh,  g_xh);
    (void)cudaGetSymbolAddress((void**)&xl,  g_xl);
    (void)cudaGetSymbolAddress((void**)&w1h, g_w1h);
    (void)cudaGetSymbolAddress((void**)&w1l, g_w1l);
    (void)cudaGetSymbolAddress((void**)&w2h, g_w2h);
    (void)cudaGetSymbolAddress((void**)&w2l, g_w2l);
    float* ao;
    (void)cudaGetSymbolAddress((void**)&ao, g_ao);

    prep_pack<<<(1024*512+255)/256, 256>>>(Wq,  w1h, w1l, 1024*512, SCALE);
    prep_pack<<<(512*512+255)/256,  256>>>(Wkv, w1h + 1024*512, w1l + 1024*512, 512*512, 1.f);
    prep_pack<<<(1024*512+255)/256, 256>>>(Wproj, w2h, w2l, 1024*512, 1.f);
    prep_pack<<<(ROWS*512+255)/256, 256>>>(x, xh, xl, ROWS*512, 1.f);

    qkv_gemm<<<dim3(QKVN/128, ROWS/128), 256, GEMM_SMEM>>>();
    prep_v<<<512, 256>>>();
    attn_kernel<<<dim3(SEQ/128, NH, BATCH), 256>>>();

    prep_pack<<<(ROWS*512+255)/256, 256>>>(ao, xh, xl, ROWS*512, 1.f);
    proj_gemm<<<dim3(DIMC/128, ROWS/128), 256, GEMM_SMEM>>>(bproj, out);
}